// round 8
// baseline (speedup 1.0000x reference)
#include <cuda_runtime.h>
#include <cuda_bf16.h>
#include <math.h>

#define T_SEQ   2048
#define NH      16
#define HD      64
#define DM      1024
#define BATCH   2
#define MROWS   (BATCH * T_SEQ)   // 4096
#define L_CH    64
#define NCH     (T_SEQ / L_CH)    // 32
#define BH      (BATCH * NH)      // 32

// GEMM tiling
#define KC 32
#define ARS 40                      // padded row stride in bf16 (80 B)
#define MATB (128 * ARS * 2)        // 10240 B per matrix image
#define PAIRB (2 * MATB)            // 20480 B = hi|lo pair
#define STGB (2 * PAIRB)            // 40960 B per stage
#define NSTG 3
#define NBK  (DM / KC)              // 32 k-chunks
#define PK(t, c) (((size_t)(t) * NBK + (c)) * PAIRB)

// retention smem tiling: 64 x 64 bf16 images, 144 B row stride
#define RRS 144
#define RIMG (64 * RRS)             // 9216 B per image
#define R_QH (0 * RIMG)
#define R_QL (1 * RIMG)
#define R_KH (2 * RIMG)
#define R_KL (3 * RIMG)
#define R_VTH (4 * RIMG)
#define R_VTL (5 * RIMG)
#define R_STH (6 * RIMG)
#define R_STL (7 * RIMG)
#define R_PH (8 * RIMG)
#define R_PL (9 * RIMG)
#define RSMEM (10 * RIMG)           // 92160 B

// ---------------------------------------------------------------------------
// Scratch (device globals: allocation-free per harness rules)
// ---------------------------------------------------------------------------
__device__ __align__(16) float g_QKV[3 * (size_t)BH * T_SEQ * HD];
__device__ __align__(16) float g_O[(size_t)BH * T_SEQ * HD];
__device__ __align__(16) float g_G[(size_t)BH * NCH * HD * HD];
__device__ __align__(16) float g_S[(size_t)BH * NCH * HD * HD];
__device__ double g_PS[BH * 16];
__device__ double g_PS2[BH * 16];
__device__ float g_MU[BH];
__device__ float g_RS[BH];

__device__ __align__(128) char g_XP[(size_t)32 * NBK * PAIRB];
__device__ __align__(128) char g_WP[(size_t)32 * NBK * PAIRB];
__device__ __align__(128) char g_YP[(size_t)32 * NBK * PAIRB];

// ---------------------------------------------------------------------------
// Baseline-PTX helpers (all sm_80/sm_90 baseline: legal on compute_103)
// ---------------------------------------------------------------------------
__device__ __forceinline__ unsigned smem_u32(const void* p) {
    unsigned a;
    asm("{ .reg .u64 t; cvta.to.shared.u64 t, %1; cvt.u32.u64 %0, t; }"
        : "=r"(a) : "l"(p));
    return a;
}
__device__ __forceinline__ void ldsm_x4(unsigned* r, unsigned addr) {
    asm volatile("ldmatrix.sync.aligned.m8n8.x4.shared.b16 {%0,%1,%2,%3}, [%4];"
                 : "=r"(r[0]), "=r"(r[1]), "=r"(r[2]), "=r"(r[3]) : "r"(addr));
}
__device__ __forceinline__ void mma_bf16(float* d, const unsigned* a, const unsigned* b) {
    asm volatile(
        "mma.sync.aligned.m16n8k16.row.col.f32.bf16.bf16.f32 "
        "{%0,%1,%2,%3}, {%4,%5,%6,%7}, {%8,%9}, {%0,%1,%2,%3};"
        : "+f"(d[0]), "+f"(d[1]), "+f"(d[2]), "+f"(d[3])
        : "r"(a[0]), "r"(a[1]), "r"(a[2]), "r"(a[3]), "r"(b[0]), "r"(b[1]));
}

#define MBAR_INIT(sa, n) \
    asm volatile("mbarrier.init.shared.b64 [%0], %1;" :: "r"((unsigned)(sa)), "r"((unsigned)(n)) : "memory")
#define MBAR_EXPECT(sa, bytes) \
    asm volatile("mbarrier.arrive.expect_tx.shared.b64 _, [%0], %1;" \
                 :: "r"((unsigned)(sa)), "r"((unsigned)(bytes)) : "memory")
#define CP_BULK(dst, src, nbytes, mbar) \
    asm volatile("cp.async.bulk.shared::cluster.global.mbarrier::complete_tx::bytes [%0], [%1], %2, [%3];" \
                 :: "r"((unsigned)(dst)), "l"(src), "r"((unsigned)(nbytes)), "r"((unsigned)(mbar)) : "memory")

#define MBAR_WAIT(sa, ph) do {                                                  \
    unsigned _m = (unsigned)(sa), _p = (unsigned)(ph), _d;                      \
    asm volatile(                                                               \
        "{\n\t.reg .pred p;\n\t"                                                \
        "mbarrier.try_wait.parity.acquire.cta.shared::cta.b64 p, [%1], %2;\n\t" \
        "selp.b32 %0, 1, 0, p;\n\t}"                                            \
        : "=r"(_d) : "r"(_m), "r"(_p) : "memory");                              \
    if (!_d) {                                                                  \
        asm volatile(                                                           \
            "{\n\t.reg .pred P1;\n\t"                                           \
            "WL_%=:\n\t"                                                        \
            "mbarrier.try_wait.parity.acquire.cta.shared::cta.b64 P1, [%0], %1, 0x989680;\n\t" \
            "@P1 bra.uni WD_%=;\n\t"                                            \
            "bra.uni WL_%=;\n\t"                                                \
            "WD_%=:\n\t}"                                                       \
            :: "r"(_m), "r"(_p) : "memory");                                    \
    }                                                                           \
} while (0)

// split helpers
__device__ __forceinline__ void split2(float x0, float x1, unsigned& hu, unsigned& lu) {
    __nv_bfloat16 h0 = __float2bfloat16(x0), h1 = __float2bfloat16(x1);
    __nv_bfloat16 l0 = __float2bfloat16(x0 - __bfloat162float(h0));
    __nv_bfloat16 l1 = __float2bfloat16(x1 - __bfloat162float(h1));
    hu = (unsigned)__bfloat16_as_ushort(h0) | ((unsigned)__bfloat16_as_ushort(h1) << 16);
    lu = (unsigned)__bfloat16_as_ushort(l0) | ((unsigned)__bfloat16_as_ushort(l1) << 16);
}
__device__ __forceinline__ void split1(float x, unsigned short& h, unsigned short& l) {
    __nv_bfloat16 h0 = __float2bfloat16(x);
    __nv_bfloat16 l0 = __float2bfloat16(x - __bfloat162float(h0));
    h = __bfloat16_as_ushort(h0);
    l = __bfloat16_as_ushort(l0);
}
__device__ __forceinline__ void split8(const float* v, uint4& hv, uint4& lv) {
    unsigned hu[4], lu[4];
#pragma unroll
    for (int j = 0; j < 4; j++) split2(v[2 * j], v[2 * j + 1], hu[j], lu[j]);
    hv = make_uint4(hu[0], hu[1], hu[2], hu[3]);
    lv = make_uint4(lu[0], lu[1], lu[2], lu[3]);
}

// ---------------------------------------------------------------------------
// Packers: fp32 row-major -> chunk-major padded hi/lo images
// ---------------------------------------------------------------------------
__global__ __launch_bounds__(256) void pack_split(
    const float* __restrict__ X, char* __restrict__ P, int tile_base)
{
    const int gid = blockIdx.x * 256 + threadIdx.x;
    const int m   = gid >> 7;
    const int rem = gid & 127;
    const int c   = rem >> 2;
    const int c16 = rem & 3;
    const float* src = X + (size_t)m * DM + c * KC + c16 * 8;
    float v[8];
    float4 a = *(const float4*)src;
    float4 b = *(const float4*)(src + 4);
    v[0] = a.x; v[1] = a.y; v[2] = a.z; v[3] = a.w;
    v[4] = b.x; v[5] = b.y; v[6] = b.z; v[7] = b.w;
    uint4 hv, lv;
    split8(v, hv, lv);
    char* dst = P + PK(tile_base + (m >> 7), c) + (m & 127) * (ARS * 2) + c16 * 16;
    *(uint4*)dst = hv;
    *(uint4*)(dst + MATB) = lv;
}

// ---------------------------------------------------------------------------
// mma.sync GEMM, packed tiles, cp.async.bulk, 3-term bf16 split.
// ---------------------------------------------------------------------------
__global__ __launch_bounds__(256) void gemm_mma(
    const char* __restrict__ Ap, const char* __restrict__ Bp,
    float* __restrict__ C, int N, int layout)
{
    extern __shared__ char smc[];
    const unsigned sb = smem_u32(smc);
    const unsigned sdata = sb + 128;
    const int tid = threadIdx.x;
    const int wid = tid >> 5;
    const int lane = tid & 31;
    const int bm = blockIdx.y, bn = blockIdx.x;
    const int wm = wid & 1;
    const int wn = wid >> 1;

    if (tid == 0) {
        MBAR_INIT(sb + 0, 1);
        MBAR_INIT(sb + 8, 1);
        MBAR_INIT(sb + 16, 1);
    }
    __syncthreads();

    auto issue = [&](int c, int s) {
        unsigned mb = sb + s * 8;
        MBAR_EXPECT(mb, STGB);
        unsigned dst = sdata + s * STGB;
        CP_BULK(dst,         Ap + PK(bm, c), PAIRB, mb);
        CP_BULK(dst + PAIRB, Bp + PK(bn, c), PAIRB, mb);
    };

    if (tid == 0) { issue(0, 0); issue(1, 1); }

    float d[16][4];
#pragma unroll
    for (int f = 0; f < 16; f++)
#pragma unroll
        for (int j = 0; j < 4; j++) d[f][j] = 0.f;

    for (int c = 0; c < NBK; c++) {
        const int s = c % NSTG;
        MBAR_WAIT(sb + s * 8, (c / NSTG) & 1);

        const unsigned base = sdata + s * STGB;
#pragma unroll
        for (int kk = 0; kk < KC; kk += 16) {
            unsigned Ahf[4][4], Alf[4][4];
#pragma unroll
            for (int fm = 0; fm < 4; fm++) {
                unsigned row = wm * 64 + fm * 16 + (lane & 15);
                unsigned col = kk + (lane >> 4) * 8;
                unsigned addr = base + row * (ARS * 2) + col * 2;
                ldsm_x4(Ahf[fm], addr);
                ldsm_x4(Alf[fm], addr + MATB);
            }
            unsigned Bhf[4][2], Blf[4][2];
#pragma unroll
            for (int fnp = 0; fnp < 2; fnp++) {
                unsigned row = wn * 32 + fnp * 16 + (lane & 15);
                unsigned col = kk + (lane >> 4) * 8;
                unsigned addr = base + PAIRB + row * (ARS * 2) + col * 2;
                unsigned bH[4], bL[4];
                ldsm_x4(bH, addr);
                ldsm_x4(bL, addr + MATB);
                Bhf[2 * fnp][0] = bH[0]; Bhf[2 * fnp][1] = bH[2];
                Bhf[2 * fnp + 1][0] = bH[1]; Bhf[2 * fnp + 1][1] = bH[3];
                Blf[2 * fnp][0] = bL[0]; Blf[2 * fnp][1] = bL[2];
                Blf[2 * fnp + 1][0] = bL[1]; Blf[2 * fnp + 1][1] = bL[3];
            }
#pragma unroll
            for (int fm = 0; fm < 4; fm++)
#pragma unroll
                for (int fn = 0; fn < 4; fn++) {
                    float* acc = d[fm * 4 + fn];
                    mma_bf16(acc, Ahf[fm], Bhf[fn]);
                    mma_bf16(acc, Ahf[fm], Blf[fn]);
                    mma_bf16(acc, Alf[fm], Bhf[fn]);
                }
        }
        __syncthreads();
        if (tid == 0 && c + 2 < NBK) issue(c + 2, (c + 2) % NSTG);
    }

    const int mloc0 = bm * 128 + wm * 64 + (lane >> 2);
    const int nloc0 = bn * 128 + wn * 32 + (lane & 3) * 2;
#pragma unroll
    for (int fm = 0; fm < 4; fm++) {
#pragma unroll
        for (int fn = 0; fn < 4; fn++) {
            const float* acc = d[fm * 4 + fn];
            const int n = nloc0 + fn * 8;
#pragma unroll
            for (int rr = 0; rr < 2; rr++) {
                const int m = mloc0 + fm * 16 + rr * 8;
                float2 v = {acc[rr * 2], acc[rr * 2 + 1]};
                if (layout == 0) {
                    *(float2*)(C + (size_t)m * N + n) = v;
                } else {
                    const int which = n >> 10;
                    const int nn = n & 1023;
                    const int h = nn >> 6, dd = nn & 63;
                    const int bb = m >> 11, t = m & 2047;
                    float* dst = C + (size_t)which * (BH * T_SEQ * HD)
                               + (((size_t)(bb * NH + h) * T_SEQ + t) * HD + dd);
                    *(float2*)dst = v;
                }
            }
        }
    }
}

// ---------------------------------------------------------------------------
// Pass A: G_c[d1][d2] = sum_b gamma^(L-b) K[b][d1] V[b][d2]  (SIMT)
// ---------------------------------------------------------------------------
__global__ __launch_bounds__(256) void chunk_state(
    const float* __restrict__ K, const float* __restrict__ V,
    float* __restrict__ G)
{
    __shared__ __align__(16) float Ks[L_CH][HD];
    __shared__ __align__(16) float Vs[L_CH][HD];

    const int c  = blockIdx.x;
    const int bh = blockIdx.y;
    const int h  = bh & (NH - 1);
    const int tid = threadIdx.x;
    const int rB = (tid >> 4) * 4;
    const int cB = (tid & 15) * 4;

    const double g_d = 1.0 - exp2(-5.0 - 0.5 * (double)h);
    const float lg = (float)log2(g_d);

    const float* Kg = K + ((size_t)bh * T_SEQ + c * L_CH) * HD;
    const float* Vg = V + ((size_t)bh * T_SEQ + c * L_CH) * HD;
#pragma unroll
    for (int u = 0; u < 4; u++) {
        int idx = tid + u * 256;
        int t = idx >> 4;
        int d4 = (idx & 15) * 4;
        float w = exp2f((float)(L_CH - t) * lg);
        float4 kv = *(const float4*)(Kg + t * HD + d4);
        kv.x *= w; kv.y *= w; kv.z *= w; kv.w *= w;
        *(float4*)&Ks[t][d4] = kv;
        *(float4*)&Vs[t][d4] = *(const float4*)(Vg + t * HD + d4);
    }
    __syncthreads();

    float acc[4][4];
#pragma unroll
    for (int i = 0; i < 4; i++)
#pragma unroll
        for (int j = 0; j < 4; j++) acc[i][j] = 0.f;

#pragma unroll 4
    for (int k = 0; k < L_CH; k++) {
        float4 ak = *(const float4*)&Ks[k][rB];
        float4 bk = *(const float4*)&Vs[k][cB];
        float ar[4] = {ak.x, ak.y, ak.z, ak.w};
#pragma unroll
        for (int i = 0; i < 4; i++) {
            acc[i][0] += ar[i] * bk.x; acc[i][1] += ar[i] * bk.y;
            acc[i][2] += ar[i] * bk.z; acc[i][3] += ar[i] * bk.w;
        }
    }

    float* Gg = G + ((size_t)bh * NCH + c) * HD * HD;
#pragma unroll
    for (int i = 0; i < 4; i++) {
        float4 v = {acc[i][0], acc[i][1], acc[i][2], acc[i][3]};
        *(float4*)&Gg[(rB + i) * HD + cB] = v;
    }
}

// ---------------------------------------------------------------------------
// Pass B: S_0 = 0 ; S_c = gamma^L * S_{c-1} + G_{c-1}
// ---------------------------------------------------------------------------
__global__ __launch_bounds__(256) void state_scan(
    const float* __restrict__ G, float* __restrict__ S)
{
    const int bh = blockIdx.x;
    const int h  = bh & (NH - 1);
    const int tid = threadIdx.x;
    const double g_d = 1.0 - exp2(-5.0 - 0.5 * (double)h);
    const float decL = (float)exp2((double)L_CH * log2(g_d));

    const size_t base = (size_t)bh * NCH * HD * HD;
    float s[16];
#pragma unroll
    for (int u = 0; u < 16; u++) s[u] = 0.f;

    for (int c = 0; c < NCH; c++) {
        const size_t off = base + (size_t)c * HD * HD;
#pragma unroll
        for (int u = 0; u < 16; u++) {
            int e = tid + u * 256;
            S[off + e] = s[u];
            s[u] = s[u] * decL + G[off + e];
        }
    }
}

// ---------------------------------------------------------------------------
// Pass C (tensor cores): decay folded into operands.
//   Q'[t] = Q[t] * gamma^t / 8 ; K'[u] = K[u] * gamma^-u
//   O = tril(Q' K'^T) @ V + Q' @ S      (3-term bf16 split everywhere)
// grid (NCH, BH), 256 thr, 8 warps: wm=wid&3 (16 rows), wn=wid>>2 (32 cols)
// ---------------------------------------------------------------------------
__global__ __launch_bounds__(256) void retention_mma(
    const float* __restrict__ Q, const float* __restrict__ K,
    const float* __restrict__ V, const float* __restrict__ S,
    float* __restrict__ O)
{
    extern __shared__ char sr[];
    const unsigned sb = smem_u32(sr);
    const int c  = blockIdx.x;
    const int bh = blockIdx.y;
    const int h  = bh & (NH - 1);
    const int r0 = c * L_CH;
    const int tid = threadIdx.x;
    const int wid = tid >> 5;
    const int lane = tid & 31;
    const int wm = wid & 3;
    const int wn = wid >> 2;

    const double g_d = 1.0 - exp2(-5.0 - 0.5 * (double)h);
    const float lg = (float)log2(g_d);

    const float* Qg = Q + ((size_t)bh * T_SEQ + r0) * HD;
    const float* Kg = K + ((size_t)bh * T_SEQ + r0) * HD;
    const float* Vg = V + ((size_t)bh * T_SEQ + r0) * HD;
    const float* Sg = S + ((size_t)bh * NCH + c) * HD * HD;

    // load + scale + split (+ transpose V, S)
#pragma unroll
    for (int u = 0; u < 4; u++) {
        int idx = tid + u * 256;
        int t = idx >> 4;
        int d4 = (idx & 15) * 4;
        const float fq = exp2f((float)t * lg) * 0.125f;
        const float fk = exp2f(-(float)t * lg);

        float4 qv = *(const float4*)(Qg + t * HD + d4);
        qv.x *= fq; qv.y *= fq; qv.z *= fq; qv.w *= fq;
        unsigned h0, l0, h1, l1;
        split2(qv.x, qv.y, h0, l0); split2(qv.z, qv.w, h1, l1);
        char* qd = sr + R_QH + t * RRS + d4 * 2;
        *(unsigned*)qd = h0; *(unsigned*)(qd + 4) = h1;
        *(unsigned*)(qd + RIMG) = l0; *(unsigned*)(qd + RIMG + 4) = l1;

        float4 kv = *(const float4*)(Kg + t * HD + d4);
        kv.x *= fk; kv.y *= fk; kv.z *= fk; kv.w *= fk;
        split2(kv.x, kv.y, h0, l0); split2(kv.z, kv.w, h1, l1);
        char* kd = sr + R_KH + t * RRS + d4 * 2;
        *(unsigned*)kd = h0; *(unsigned*)(kd + 4) = h1;
        *(unsigned*)(kd + RIMG) = l0; *(unsigned*)(kd + RIMG + 4) = l1;

        float4 vv = *(const float4*)(Vg + t * HD + d4);
        float4 sv = *(const float4*)(Sg + t * HD + d4);
        float va[4] = {vv.x, vv.y, vv.z, vv.w};
        float sa[4] = {sv.x, sv.y, sv.z, sv.w};
#pragma unroll
        for (int i = 0; i < 4; i++) {
            unsigned short hh, ll;
            split1(va[i], hh, ll);
            *(unsigned short*)(sr + R_VTH + (d4 + i) * RRS + t * 2) = hh;
            *(unsigned short*)(sr + R_VTL + (d4 + i) * RRS + t * 2) = ll;
            split1(sa[i], hh, ll);
            *(unsigned short*)(sr + R_STH + (d4 + i) * RRS + t * 2) = hh;
            *(unsigned short*)(sr + R_STL + (d4 + i) * RRS + t * 2) = ll;
        }
    }
    __syncthreads();

    float accC[4][4], accP[4][4];
#pragma unroll
    for (int f = 0; f < 4; f++)
#pragma unroll
        for (int j = 0; j < 4; j++) { accC[f][j] = 0.f; accP[f][j] = 0.f; }

    // phase 1: accC = Q'@S (via ST), accP = Q'@K'^T
#pragma unroll
    for (int ks = 0; ks < 4; ks++) {
        const int kk = ks * 16;
        unsigned aH[4], aL[4];
        unsigned aaddr = sb + R_QH + (wm * 16 + (lane & 15)) * RRS + (kk + (lane >> 4) * 8) * 2;
        ldsm_x4(aH, aaddr);
        ldsm_x4(aL, aaddr + RIMG);
#pragma unroll
        for (int fnp = 0; fnp < 2; fnp++) {
            const unsigned brow = (wn * 32 + fnp * 16 + (lane & 15)) * RRS + (kk + (lane >> 4) * 8) * 2;
            unsigned sH[4], sL[4], kH[4], kL[4];
            ldsm_x4(sH, sb + R_STH + brow);
            ldsm_x4(sL, sb + R_STL + brow);
            ldsm_x4(kH, sb + R_KH + brow);
            ldsm_x4(kL, sb + R_KL + brow);
#pragma unroll
            for (int half = 0; half < 2; half++) {
                const int fn = 2 * fnp + half;
                unsigned bh0[2] = {sH[half], sH[half + 2]};
                unsigned bl0[2] = {sL[half], sL[half + 2]};
                mma_bf16(accC[fn], aH, bh0);
                mma_bf16(accC[fn], aH, bl0);
                mma_bf16(accC[fn], aL, bh0);
                unsigned bh1[2] = {kH[half], kH[half + 2]};
                unsigned bl1[2] = {kL[half], kL[half + 2]};
                mma_bf16(accP[fn], aH, bh1);
                mma_bf16(accP[fn], aH, bl1);
                mma_bf16(accP[fn], aL, bh1);
            }
        }
    }

    // mask P (zero where u > t), split, store to smem
#pragma unroll
    for (int fn = 0; fn < 4; fn++) {
#pragma unroll
        for (int rr = 0; rr < 2; rr++) {
            const int row = wm * 16 + (lane >> 2) + rr * 8;
            const int col = wn * 32 + fn * 8 + (lane & 3) * 2;
            float p0 = (col     <= row) ? accP[fn][rr * 2]     : 0.f;
            float p1 = (col + 1 <= row) ? accP[fn][rr * 2 + 1] : 0.f;
            unsigned hu, lu;
            split2(p0, p1, hu, lu);
            char* pd = sr + R_PH + row * RRS + col * 2;
            *(unsigned*)pd = hu;
            *(unsigned*)(pd + RIMG) = lu;
        }
    }
    __syncthreads();

    // phase 2: accC += P @ V (via VT)
#pragma unroll
    for (int ks = 0; ks < 4; ks++) {
        const int kk = ks * 16;
        unsigned aH[4], aL[4];
        unsigned aaddr = sb + R_PH + (wm * 16 + (lane & 15)) * RRS + (kk + (lane >> 4) * 8) * 2;
        ldsm_x4(aH, aaddr);
        ldsm_x4(aL, aaddr + RIMG);
#pragma unroll
        for (int fnp = 0; fnp < 2; fnp++) {
            const unsigned brow = (wn * 32 + fnp * 16 + (lane & 15)) * RRS + (kk + (lane >> 4) * 8) * 2;
            unsigned vH[4], vL[4];
            ldsm_x4(vH, sb + R_VTH + brow);
            ldsm_x4(vL, sb + R_VTL + brow);
#pragma unroll
            for (int half = 0; half < 2; half++) {
                const int fn = 2 * fnp + half;
                unsigned bh0[2] = {vH[half], vH[half + 2]};
                unsigned bl0[2] = {vL[half], vL[half + 2]};
                mma_bf16(accC[fn], aH, bh0);
                mma_bf16(accC[fn], aH, bl0);
                mma_bf16(accC[fn], aL, bh0);
            }
        }
    }

    // store O
    float* Og = O + ((size_t)bh * T_SEQ + r0) * HD;
#pragma unroll
    for (int fn = 0; fn < 4; fn++) {
#pragma unroll
        for (int rr = 0; rr < 2; rr++) {
            const int row = wm * 16 + (lane >> 2) + rr * 8;
            const int col = wn * 32 + fn * 8 + (lane & 3) * 2;
            float2 v = {accC[fn][rr * 2], accC[fn][rr * 2 + 1]};
            *(float2*)(Og + (size_t)row * HD + col) = v;
        }
    }
}

// ---------------------------------------------------------------------------
// GroupNorm, three stages (apply writes the packed y tiles directly)
// ---------------------------------------------------------------------------
__global__ __launch_bounds__(256) void gn_partial(const float* __restrict__ O)
{
    const int bh   = blockIdx.x >> 4;
    const int slab = blockIdx.x & 15;
    const int tid  = threadIdx.x;
    const float* base = O + (size_t)bh * (T_SEQ * HD) + slab * 8192;

    double s = 0.0, s2 = 0.0;
#pragma unroll
    for (int u = 0; u < 8; u++) {
        float4 v = *(const float4*)(base + (tid + u * 256) * 4);
        s  += (double)v.x + v.y + v.z + v.w;
        s2 += (double)v.x * v.x + (double)v.y * v.y + (double)v.z * v.z + (double)v.w * v.w;
    }
    __shared__ double sh[256], sh2[256];
    sh[tid] = s; sh2[tid] = s2;
    __syncthreads();
    for (int off = 128; off > 0; off >>= 1) {
        if (tid < off) { sh[tid] += sh[tid + off]; sh2[tid] += sh2[tid + off]; }
        __syncthreads();
    }
    if (tid == 0) { g_PS[blockIdx.x] = sh[0]; g_PS2[blockIdx.x] = sh2[0]; }
}

__global__ void gn_finalize()
{
    const int bh = blockIdx.x;
    const int tid = threadIdx.x;
    double s = 0.0, s2 = 0.0;
    if (tid < 16) { s = g_PS[bh * 16 + tid]; s2 = g_PS2[bh * 16 + tid]; }
#pragma unroll
    for (int off = 8; off > 0; off >>= 1) {
        s  += __shfl_down_sync(0xffffffff, s,  off);
        s2 += __shfl_down_sync(0xffffffff, s2, off);
    }
    if (tid == 0) {
        const double N = (double)(T_SEQ * HD);
        double mu  = s / N;
        double var = s2 / N - mu * mu;
        g_MU[bh] = (float)mu;
        g_RS[bh] = (float)rsqrt(var + 1e-5);
    }
}

__global__ __launch_bounds__(256) void gn_apply(
    const float* __restrict__ O, const float* __restrict__ gw,
    const float* __restrict__ gb, char* __restrict__ YP)
{
    const int f = blockIdx.x * 256 + threadIdx.x;
    const int bh = f >> 15;
    const int rem = f & 32767;
    const int t = rem >> 4;
    const int d4 = (rem & 15) * 4;
    const int b = bh >> 4, h = bh & 15;

    const float mu = g_MU[bh], rs = g_RS[bh];
    float4 v = *(const float4*)(O + ((size_t)bh * T_SEQ + t) * HD + d4);
    float4 w = *(const float4*)(gw + h * HD + d4);
    float4 bb = *(const float4*)(gb + h * HD + d4);
    float r[4];
    r[0] = (v.x - mu) * rs * w.x + bb.x;
    r[1] = (v.y - mu) * rs * w.y + bb.y;
    r[2] = (v.z - mu) * rs * w.z + bb.z;
    r[3] = (v.w - mu) * rs * w.w + bb.w;

    unsigned hu[2], lu[2];
    split2(r[0], r[1], hu[0], lu[0]);
    split2(r[2], r[3], hu[1], lu[1]);
    const int m = b * T_SEQ + t;
    const int k0 = h * HD + d4;
    char* dst = YP + PK(m >> 7, k0 >> 5) + (m & 127) * (ARS * 2) + (k0 & 31) * 2;
    uint2 hv = {hu[0], hu[1]};
    uint2 lv = {lu[0], lu[1]};
    *(uint2*)dst = hv;
    *(uint2*)(dst + MATB) = lv;
}

// ---------------------------------------------------------------------------
extern "C" void kernel_launch(void* const* d_in, const int* in_sizes, int n_in,
                              void* d_out, int out_size)
{
    const float* x   = (const float*)d_in[0];
    const float* Wq  = (const float*)d_in[1];
    const float* Wk  = (const float*)d_in[2];
    const float* Wv  = (const float*)d_in[3];
    const float* Wo  = (const float*)d_in[4];
    const float* gnw = (const float*)d_in[5];
    const float* gnb = (const float*)d_in[6];
    float* out = (float*)d_out;

    float *qkv, *o, *gg, *ss;
    char *xp, *wp, *yp;
    cudaGetSymbolAddress((void**)&qkv, g_QKV);
    cudaGetSymbolAddress((void**)&o, g_O);
    cudaGetSymbolAddress((void**)&gg, g_G);
    cudaGetSymbolAddress((void**)&ss, g_S);
    cudaGetSymbolAddress((void**)&xp, g_XP);
    cudaGetSymbolAddress((void**)&wp, g_WP);
    cudaGetSymbolAddress((void**)&yp, g_YP);

    float* q = qkv;
    float* k = qkv + 1 * (size_t)BH * T_SEQ * HD;
    float* v = qkv + 2 * (size_t)BH * T_SEQ * HD;

    const int gemm_smem = 128 + NSTG * STGB;
    cudaFuncSetAttribute(gemm_mma, cudaFuncAttributeMaxDynamicSharedMemorySize, gemm_smem);
    cudaFuncSetAttribute(retention_mma, cudaFuncAttributeMaxDynamicSharedMemorySize, RSMEM);

    pack_split<<<2048, 256>>>(x, xp, 0);
    pack_split<<<512, 256>>>(Wq, wp, 0);
    pack_split<<<512, 256>>>(Wk, wp, 8);
    pack_split<<<512, 256>>>(Wv, wp, 16);
    pack_split<<<512, 256>>>(Wo, wp, 24);

    dim3 gQKV(3 * DM / 128, MROWS / 128);
    gemm_mma<<<gQKV, 256, gemm_smem>>>(xp, wp, qkv, 3 * DM, 1);

    chunk_state<<<dim3(NCH, BH), 256>>>(k, v, gg);
    state_scan<<<BH, 256>>>(gg, ss);
    retention_mma<<<dim3(NCH, BH), 256, RSMEM>>>(q, k, v, ss, o);

    gn_partial<<<BH * 16, 256>>>(o);
    gn_finalize<<<BH, 32>>>();
    gn_apply<<<(MROWS * DM) / (4 * 256), 256>>>(o, gnw, gnb, yp);

    dim3 gO(DM / 128, MROWS / 128);
    gemm_mma<<<gO, 256, gemm_smem>>>(yp, wp + (size_t)24 * NBK * PAIRB, out, DM, 0);
}

// round 10
// speedup vs baseline: 1.0569x; 1.0569x over previous
#include <cuda_runtime.h>
#include <cuda_bf16.h>
#include <math.h>

#define T_SEQ   2048
#define NH      16
#define HD      64
#define DM      1024
#define BATCH   2
#define MROWS   (BATCH * T_SEQ)   // 4096
#define L_CH    64
#define NCH     (T_SEQ / L_CH)    // 32
#define BH      (BATCH * NH)      // 32

// GEMM tiling
#define KC 32
#define ARS 40                      // padded row stride in bf16 (80 B)
#define MATB (128 * ARS * 2)        // 10240 B per matrix image
#define PAIRB (2 * MATB)            // 20480 B = hi|lo pair
#define STGB (2 * PAIRB)            // 40960 B per stage
#define NSTG 3
#define NBK  (DM / KC)              // 32 k-chunks
#define PK(t, c) (((size_t)(t) * NBK + (c)) * PAIRB)

// ---------------------------------------------------------------------------
// Scratch (device globals: allocation-free per harness rules)
// ---------------------------------------------------------------------------
__device__ __align__(16) float g_QKV[3 * (size_t)BH * T_SEQ * HD];
__device__ __align__(16) float g_O[(size_t)BH * T_SEQ * HD];
__device__ __align__(16) float g_G[(size_t)BH * NCH * HD * HD];
__device__ __align__(16) float g_S[(size_t)BH * NCH * HD * HD];
__device__ double g_PS[BH * NCH];
__device__ double g_PS2[BH * NCH];
__device__ float g_MU[BH];
__device__ float g_RS[BH];

__device__ __align__(128) char g_XP[(size_t)32 * NBK * PAIRB];
__device__ __align__(128) char g_WP[(size_t)32 * NBK * PAIRB];
__device__ __align__(128) char g_YP[(size_t)32 * NBK * PAIRB];

// ---------------------------------------------------------------------------
// Baseline-PTX helpers (all sm_80/sm_90 baseline: legal on compute_103)
// ---------------------------------------------------------------------------
__device__ __forceinline__ unsigned smem_u32(const void* p) {
    unsigned a;
    asm("{ .reg .u64 t; cvta.to.shared.u64 t, %1; cvt.u32.u64 %0, t; }"
        : "=r"(a) : "l"(p));
    return a;
}
__device__ __forceinline__ void ldsm_x4(unsigned* r, unsigned addr) {
    asm volatile("ldmatrix.sync.aligned.m8n8.x4.shared.b16 {%0,%1,%2,%3}, [%4];"
                 : "=r"(r[0]), "=r"(r[1]), "=r"(r[2]), "=r"(r[3]) : "r"(addr));
}
__device__ __forceinline__ void ldsm_x2(unsigned* r, unsigned addr) {
    asm volatile("ldmatrix.sync.aligned.m8n8.x2.shared.b16 {%0,%1}, [%2];"
                 : "=r"(r[0]), "=r"(r[1]) : "r"(addr));
}
__device__ __forceinline__ void mma_bf16(float* d, const unsigned* a, const unsigned* b) {
    asm volatile(
        "mma.sync.aligned.m16n8k16.row.col.f32.bf16.bf16.f32 "
        "{%0,%1,%2,%3}, {%4,%5,%6,%7}, {%8,%9}, {%0,%1,%2,%3};"
        : "+f"(d[0]), "+f"(d[1]), "+f"(d[2]), "+f"(d[3])
        : "r"(a[0]), "r"(a[1]), "r"(a[2]), "r"(a[3]), "r"(b[0]), "r"(b[1]));
}

#define MBAR_INIT(sa, n) \
    asm volatile("mbarrier.init.shared.b64 [%0], %1;" :: "r"((unsigned)(sa)), "r"((unsigned)(n)) : "memory")
#define MBAR_EXPECT(sa, bytes) \
    asm volatile("mbarrier.arrive.expect_tx.shared.b64 _, [%0], %1;" \
                 :: "r"((unsigned)(sa)), "r"((unsigned)(bytes)) : "memory")
#define CP_BULK(dst, src, nbytes, mbar) \
    asm volatile("cp.async.bulk.shared::cluster.global.mbarrier::complete_tx::bytes [%0], [%1], %2, [%3];" \
                 :: "r"((unsigned)(dst)), "l"(src), "r"((unsigned)(nbytes)), "r"((unsigned)(mbar)) : "memory")

#define MBAR_WAIT(sa, ph) do {                                                  \
    unsigned _m = (unsigned)(sa), _p = (unsigned)(ph), _d;                      \
    asm volatile(                                                               \
        "{\n\t.reg .pred p;\n\t"                                                \
        "mbarrier.try_wait.parity.acquire.cta.shared::cta.b64 p, [%1], %2;\n\t" \
        "selp.b32 %0, 1, 0, p;\n\t}"                                            \
        : "=r"(_d) : "r"(_m), "r"(_p) : "memory");                              \
    if (!_d) {                                                                  \
        asm volatile(                                                           \
            "{\n\t.reg .pred P1;\n\t"                                           \
            "WL_%=:\n\t"                                                        \
            "mbarrier.try_wait.parity.acquire.cta.shared::cta.b64 P1, [%0], %1, 0x989680;\n\t" \
            "@P1 bra.uni WD_%=;\n\t"                                            \
            "bra.uni WL_%=;\n\t"                                                \
            "WD_%=:\n\t}"                                                       \
            :: "r"(_m), "r"(_p) : "memory");                                    \
    }                                                                           \
} while (0)

// split 8 fp32 -> 16B hi + 16B lo
__device__ __forceinline__ void split2(float x0, float x1, unsigned& hu, unsigned& lu) {
    __nv_bfloat16 h0 = __float2bfloat16(x0), h1 = __float2bfloat16(x1);
    __nv_bfloat16 l0 = __float2bfloat16(x0 - __bfloat162float(h0));
    __nv_bfloat16 l1 = __float2bfloat16(x1 - __bfloat162float(h1));
    hu = (unsigned)__bfloat16_as_ushort(h0) | ((unsigned)__bfloat16_as_ushort(h1) << 16);
    lu = (unsigned)__bfloat16_as_ushort(l0) | ((unsigned)__bfloat16_as_ushort(l1) << 16);
}
__device__ __forceinline__ void split8(const float* v, uint4& hv, uint4& lv) {
    unsigned hu[4], lu[4];
#pragma unroll
    for (int j = 0; j < 4; j++) split2(v[2 * j], v[2 * j + 1], hu[j], lu[j]);
    hv = make_uint4(hu[0], hu[1], hu[2], hu[3]);
    lv = make_uint4(lu[0], lu[1], lu[2], lu[3]);
}

// ---------------------------------------------------------------------------
// Packers: fp32 row-major -> chunk-major padded hi/lo images
// ---------------------------------------------------------------------------
__global__ __launch_bounds__(256) void pack_split(
    const float* __restrict__ X, char* __restrict__ P, int tile_base)
{
    const int gid = blockIdx.x * 256 + threadIdx.x;
    const int m   = gid >> 7;
    const int rem = gid & 127;
    const int c   = rem >> 2;
    const int c16 = rem & 3;
    const float* src = X + (size_t)m * DM + c * KC + c16 * 8;
    float v[8];
    float4 a = *(const float4*)src;
    float4 b = *(const float4*)(src + 4);
    v[0] = a.x; v[1] = a.y; v[2] = a.z; v[3] = a.w;
    v[4] = b.x; v[5] = b.y; v[6] = b.z; v[7] = b.w;
    uint4 hv, lv;
    split8(v, hv, lv);
    char* dst = P + PK(tile_base + (m >> 7), c) + (m & 127) * (ARS * 2) + c16 * 16;
    *(uint4*)dst = hv;
    *(uint4*)(dst + MATB) = lv;
}

// all four weights in one launch (grid 2048)
__global__ __launch_bounds__(256) void pack_w4(
    const float* __restrict__ W0, const float* __restrict__ W1,
    const float* __restrict__ W2, const float* __restrict__ W3,
    char* __restrict__ P)
{
    const int gid = blockIdx.x * 256 + threadIdx.x;   // 0..524287
    const int wsel = gid >> 17;
    const int g = gid & 131071;
    const float* W = (wsel == 0) ? W0 : (wsel == 1) ? W1 : (wsel == 2) ? W2 : W3;
    const int m   = g >> 7;
    const int rem = g & 127;
    const int c   = rem >> 2;
    const int c16 = rem & 3;
    const float* src = W + (size_t)m * DM + c * KC + c16 * 8;
    float v[8];
    float4 a = *(const float4*)src;
    float4 b = *(const float4*)(src + 4);
    v[0] = a.x; v[1] = a.y; v[2] = a.z; v[3] = a.w;
    v[4] = b.x; v[5] = b.y; v[6] = b.z; v[7] = b.w;
    uint4 hv, lv;
    split8(v, hv, lv);
    char* dst = P + PK(wsel * 8 + (m >> 7), c) + (m & 127) * (ARS * 2) + c16 * 16;
    *(uint4*)dst = hv;
    *(uint4*)(dst + MATB) = lv;
}

// ---------------------------------------------------------------------------
// mma.sync GEMM, packed tiles, cp.async.bulk, 3-term bf16 split. (round-7)
// ---------------------------------------------------------------------------
__global__ __launch_bounds__(256) void gemm_mma(
    const char* __restrict__ Ap, const char* __restrict__ Bp,
    float* __restrict__ C, int N, int layout)
{
    extern __shared__ char smc[];
    const unsigned sb = smem_u32(smc);
    const unsigned sdata = sb + 128;
    const int tid = threadIdx.x;
    const int wid = tid >> 5;
    const int lane = tid & 31;
    const int bm = blockIdx.y, bn = blockIdx.x;
    const int wm = wid & 1;
    const int wn = wid >> 1;

    if (tid == 0) {
        MBAR_INIT(sb + 0, 1);
        MBAR_INIT(sb + 8, 1);
        MBAR_INIT(sb + 16, 1);
    }
    __syncthreads();

    auto issue = [&](int c, int s) {
        unsigned mb = sb + s * 8;
        MBAR_EXPECT(mb, STGB);
        unsigned dst = sdata + s * STGB;
        CP_BULK(dst,         Ap + PK(bm, c), PAIRB, mb);
        CP_BULK(dst + PAIRB, Bp + PK(bn, c), PAIRB, mb);
    };

    if (tid == 0) { issue(0, 0); issue(1, 1); }

    float d[16][4];
#pragma unroll
    for (int f = 0; f < 16; f++)
#pragma unroll
        for (int j = 0; j < 4; j++) d[f][j] = 0.f;

    for (int c = 0; c < NBK; c++) {
        const int s = c % NSTG;
        MBAR_WAIT(sb + s * 8, (c / NSTG) & 1);

        const unsigned base = sdata + s * STGB;
#pragma unroll
        for (int kk = 0; kk < KC; kk += 16) {
            unsigned Ahf[4][4], Alf[4][4];
#pragma unroll
            for (int fm = 0; fm < 4; fm++) {
                unsigned row = wm * 64 + fm * 16 + (lane & 15);
                unsigned col = kk + (lane >> 4) * 8;
                unsigned addr = base + row * (ARS * 2) + col * 2;
                ldsm_x4(Ahf[fm], addr);
                ldsm_x4(Alf[fm], addr + MATB);
            }
            unsigned Bhf[4][2], Blf[4][2];
#pragma unroll
            for (int fn = 0; fn < 4; fn++) {
                unsigned row = wn * 32 + fn * 8 + (lane & 7);
                unsigned col = kk + ((lane >> 3) & 1) * 8;
                unsigned addr = base + PAIRB + row * (ARS * 2) + col * 2;
                ldsm_x2(Bhf[fn], addr);
                ldsm_x2(Blf[fn], addr + MATB);
            }
#pragma unroll
            for (int fm = 0; fm < 4; fm++)
#pragma unroll
                for (int fn = 0; fn < 4; fn++) {
                    float* acc = d[fm * 4 + fn];
                    mma_bf16(acc, Ahf[fm], Bhf[fn]);
                    mma_bf16(acc, Ahf[fm], Blf[fn]);
                    mma_bf16(acc, Alf[fm], Bhf[fn]);
                }
        }
        __syncthreads();
        if (tid == 0 && c + 2 < NBK) issue(c + 2, (c + 2) % NSTG);
    }

    const int mloc0 = bm * 128 + wm * 64 + (lane >> 2);
    const int nloc0 = bn * 128 + wn * 32 + (lane & 3) * 2;
#pragma unroll
    for (int fm = 0; fm < 4; fm++) {
#pragma unroll
        for (int fn = 0; fn < 4; fn++) {
            const float* acc = d[fm * 4 + fn];
            const int n = nloc0 + fn * 8;
#pragma unroll
            for (int rr = 0; rr < 2; rr++) {
                const int m = mloc0 + fm * 16 + rr * 8;
                float2 v = {acc[rr * 2], acc[rr * 2 + 1]};
                if (layout == 0) {
                    *(float2*)(C + (size_t)m * N + n) = v;
                } else {
                    const int which = n >> 10;
                    const int nn = n & 1023;
                    const int h = nn >> 6, dd = nn & 63;
                    const int bb = m >> 11, t = m & 2047;
                    float* dst = C + (size_t)which * (BH * T_SEQ * HD)
                               + (((size_t)(bb * NH + h) * T_SEQ + t) * HD + dd);
                    *(float2*)dst = v;
                }
            }
        }
    }
}

// ---------------------------------------------------------------------------
// Pass A: G_c[d1][d2] = sum_b gamma^(L-b) K[b][d1] V[b][d2]
// ---------------------------------------------------------------------------
__global__ __launch_bounds__(256) void chunk_state(
    const float* __restrict__ K, const float* __restrict__ V,
    float* __restrict__ G)
{
    __shared__ __align__(16) float Ks[L_CH][HD];
    __shared__ __align__(16) float Vs[L_CH][HD];

    const int c  = blockIdx.x;
    const int bh = blockIdx.y;
    const int h  = bh & (NH - 1);
    const int tid = threadIdx.x;
    const int rB = (tid >> 4) * 4;
    const int cB = (tid & 15) * 4;

    const double g_d = 1.0 - exp2(-5.0 - 0.5 * (double)h);
    const float lg = (float)log2(g_d);

    const float* Kg = K + ((size_t)bh * T_SEQ + c * L_CH) * HD;
    const float* Vg = V + ((size_t)bh * T_SEQ + c * L_CH) * HD;
#pragma unroll
    for (int u = 0; u < 4; u++) {
        int idx = tid + u * 256;
        int t = idx >> 4;
        int d4 = (idx & 15) * 4;
        float w = exp2f((float)(L_CH - t) * lg);
        float4 kv = *(const float4*)(Kg + t * HD + d4);
        kv.x *= w; kv.y *= w; kv.z *= w; kv.w *= w;
        *(float4*)&Ks[t][d4] = kv;
        *(float4*)&Vs[t][d4] = *(const float4*)(Vg + t * HD + d4);
    }
    __syncthreads();

    float acc[4][4];
#pragma unroll
    for (int i = 0; i < 4; i++)
#pragma unroll
        for (int j = 0; j < 4; j++) acc[i][j] = 0.f;

#pragma unroll 4
    for (int k = 0; k < L_CH; k++) {
        float4 ak = *(const float4*)&Ks[k][rB];
        float4 bk = *(const float4*)&Vs[k][cB];
        float ar[4] = {ak.x, ak.y, ak.z, ak.w};
#pragma unroll
        for (int i = 0; i < 4; i++) {
            acc[i][0] += ar[i] * bk.x; acc[i][1] += ar[i] * bk.y;
            acc[i][2] += ar[i] * bk.z; acc[i][3] += ar[i] * bk.w;
        }
    }

    float* Gg = G + ((size_t)bh * NCH + c) * HD * HD;
#pragma unroll
    for (int i = 0; i < 4; i++) {
        float4 v = {acc[i][0], acc[i][1], acc[i][2], acc[i][3]};
        *(float4*)&Gg[(rB + i) * HD + cB] = v;
    }
}

// ---------------------------------------------------------------------------
// Pass B: S_0 = 0 ; S_c = gamma^L * S_{c-1} + G_{c-1}
// ---------------------------------------------------------------------------
__global__ __launch_bounds__(256) void state_scan(
    const float* __restrict__ G, float* __restrict__ S)
{
    const int bh = blockIdx.x;
    const int h  = bh & (NH - 1);
    const int tid = threadIdx.x;
    const double g_d = 1.0 - exp2(-5.0 - 0.5 * (double)h);
    const float decL = (float)exp2((double)L_CH * log2(g_d));

    const size_t base = (size_t)bh * NCH * HD * HD;
    float s[16];
#pragma unroll
    for (int u = 0; u < 16; u++) s[u] = 0.f;

    for (int c = 0; c < NCH; c++) {
        const size_t off = base + (size_t)c * HD * HD;
#pragma unroll
        for (int u = 0; u < 16; u++) {
            int e = tid + u * 256;
            S[off + e] = s[u];
            s[u] = s[u] * decL + G[off + e];
        }
    }
}

// ---------------------------------------------------------------------------
// Pass C: O = gamma^a * (Q/8) @ S_c + intra-chunk decayed quadratic
// (round-7 SIMT kernel) + fused GN partial reduction per block.
// ---------------------------------------------------------------------------
__global__ __launch_bounds__(256) void retention_chunk(
    const float* __restrict__ Q, const float* __restrict__ K,
    const float* __restrict__ V, const float* __restrict__ S,
    float* __restrict__ O)
{
    extern __shared__ __align__(16) float sm[];
    float* Qs = sm;
    float* Kt = sm + 4096;
    float* Vs = sm + 8192;
    float* Ss = sm + 12288;
    float* St = sm + 16384;

    const int c  = blockIdx.x;
    const int bh = blockIdx.y;
    const int h  = bh & (NH - 1);
    const int r0 = c * L_CH;
    const int tid = threadIdx.x;
    const int rB = (tid >> 4) * 4;
    const int cB = (tid & 15) * 4;

    const double g_d = 1.0 - exp2(-5.0 - 0.5 * (double)h);
    const float lg = (float)log2(g_d);

    const float* Qg = Q + ((size_t)bh * T_SEQ + r0) * HD;
    const float* Kg = K + ((size_t)bh * T_SEQ + r0) * HD;
    const float* Vg = V + ((size_t)bh * T_SEQ + r0) * HD;
    const float* Sg = S + ((size_t)bh * NCH + c) * HD * HD;

#pragma unroll
    for (int u = 0; u < 4; u++) {
        int idx = tid + u * 256;
        int t = idx >> 4;
        int d4 = (idx & 15) * 4;
        *(float4*)&Qs[t * 64 + d4] = *(const float4*)(Qg + t * HD + d4);
        float4 kv = *(const float4*)(Kg + t * HD + d4);
        Kt[(d4 + 0) * 64 + t] = kv.x;
        Kt[(d4 + 1) * 64 + t] = kv.y;
        Kt[(d4 + 2) * 64 + t] = kv.z;
        Kt[(d4 + 3) * 64 + t] = kv.w;
        *(float4*)&Vs[t * 64 + d4] = *(const float4*)(Vg + t * HD + d4);
        *(float4*)&St[t * 64 + d4] = *(const float4*)(Sg + t * HD + d4);
    }
    __syncthreads();

    float acc[4][4];
#pragma unroll
    for (int i = 0; i < 4; i++)
#pragma unroll
        for (int j = 0; j < 4; j++) acc[i][j] = 0.f;

#pragma unroll 4
    for (int k = 0; k < HD; k++) {
        float a0 = Qs[(rB + 0) * 64 + k];
        float a1 = Qs[(rB + 1) * 64 + k];
        float a2 = Qs[(rB + 2) * 64 + k];
        float a3 = Qs[(rB + 3) * 64 + k];
        float4 bq = *(const float4*)&St[k * 64 + cB];
        acc[0][0] += a0 * bq.x; acc[0][1] += a0 * bq.y; acc[0][2] += a0 * bq.z; acc[0][3] += a0 * bq.w;
        acc[1][0] += a1 * bq.x; acc[1][1] += a1 * bq.y; acc[1][2] += a1 * bq.z; acc[1][3] += a1 * bq.w;
        acc[2][0] += a2 * bq.x; acc[2][1] += a2 * bq.y; acc[2][2] += a2 * bq.z; acc[2][3] += a2 * bq.w;
        acc[3][0] += a3 * bq.x; acc[3][1] += a3 * bq.y; acc[3][2] += a3 * bq.z; acc[3][3] += a3 * bq.w;
    }
#pragma unroll
    for (int i = 0; i < 4; i++) {
        float f = exp2f((float)(rB + i) * lg) * 0.125f;
#pragma unroll
        for (int j = 0; j < 4; j++) acc[i][j] *= f;
    }

    float s[4][4];
#pragma unroll
    for (int i = 0; i < 4; i++)
#pragma unroll
        for (int j = 0; j < 4; j++) s[i][j] = 0.f;

#pragma unroll 4
    for (int k = 0; k < HD; k++) {
        float a0 = Qs[(rB + 0) * 64 + k];
        float a1 = Qs[(rB + 1) * 64 + k];
        float a2 = Qs[(rB + 2) * 64 + k];
        float a3 = Qs[(rB + 3) * 64 + k];
        float4 bq = *(const float4*)&Kt[k * 64 + cB];
        s[0][0] += a0 * bq.x; s[0][1] += a0 * bq.y; s[0][2] += a0 * bq.z; s[0][3] += a0 * bq.w;
        s[1][0] += a1 * bq.x; s[1][1] += a1 * bq.y; s[1][2] += a1 * bq.z; s[1][3] += a1 * bq.w;
        s[2][0] += a2 * bq.x; s[2][1] += a2 * bq.y; s[2][2] += a2 * bq.z; s[2][3] += a2 * bq.w;
        s[3][0] += a3 * bq.x; s[3][1] += a3 * bq.y; s[3][2] += a3 * bq.z; s[3][3] += a3 * bq.w;
    }

#pragma unroll
    for (int i = 0; i < 4; i++) {
#pragma unroll
        for (int j = 0; j < 4; j++) {
            int di = (rB + i) - (cB + j);
            float dec = (di >= 0) ? exp2f((float)di * lg) : 0.f;
            Ss[(rB + i) * 64 + (cB + j)] = s[i][j] * 0.125f * dec;
        }
    }
    __syncthreads();

#pragma unroll 4
    for (int k = 0; k < L_CH; k++) {
        float a0 = Ss[(rB + 0) * 64 + k];
        float a1 = Ss[(rB + 1) * 64 + k];
        float a2 = Ss[(rB + 2) * 64 + k];
        float a3 = Ss[(rB + 3) * 64 + k];
        float4 bv = *(const float4*)&Vs[k * 64 + cB];
        acc[0][0] += a0 * bv.x; acc[0][1] += a0 * bv.y; acc[0][2] += a0 * bv.z; acc[0][3] += a0 * bv.w;
        acc[1][0] += a1 * bv.x; acc[1][1] += a1 * bv.y; acc[1][2] += a1 * bv.z; acc[1][3] += a1 * bv.w;
        acc[2][0] += a2 * bv.x; acc[2][1] += a2 * bv.y; acc[2][2] += a2 * bv.z; acc[2][3] += a2 * bv.w;
        acc[3][0] += a3 * bv.x; acc[3][1] += a3 * bv.y; acc[3][2] += a3 * bv.z; acc[3][3] += a3 * bv.w;
    }

    float* Og = O + ((size_t)bh * T_SEQ + r0) * HD;
#pragma unroll
    for (int i = 0; i < 4; i++) {
        float4 v = {acc[i][0], acc[i][1], acc[i][2], acc[i][3]};
        *(float4*)&Og[(rB + i) * 64 + cB] = v;
    }

    // ---- fused GN partial: block-wide sum / sumsq of this 64x64 tile ----
    double ds = 0.0, ds2 = 0.0;
#pragma unroll
    for (int i = 0; i < 4; i++)
#pragma unroll
        for (int j = 0; j < 4; j++) {
            double x = (double)acc[i][j];
            ds += x; ds2 += x * x;
        }
    __syncthreads();                 // tile reads done; reuse smem for reduction
    double* shd  = (double*)sm;      // 256 doubles
    double* shd2 = (double*)sm + 256;
    shd[tid] = ds; shd2[tid] = ds2;
    __syncthreads();
    for (int off = 128; off > 0; off >>= 1) {
        if (tid < off) { shd[tid] += shd[tid + off]; shd2[tid] += shd2[tid + off]; }
        __syncthreads();
    }
    if (tid == 0) {
        g_PS[bh * NCH + c]  = shd[0];
        g_PS2[bh * NCH + c] = shd2[0];
    }
}

// ---------------------------------------------------------------------------
// GroupNorm finalize (32 partials per bh) + apply (writes packed y tiles)
// ---------------------------------------------------------------------------
__global__ void gn_finalize()
{
    const int bh = blockIdx.x;
    const int tid = threadIdx.x;   // 32 threads
    double s  = g_PS[bh * NCH + tid];
    double s2 = g_PS2[bh * NCH + tid];
#pragma unroll
    for (int off = 16; off > 0; off >>= 1) {
        s  += __shfl_down_sync(0xffffffff, s,  off);
        s2 += __shfl_down_sync(0xffffffff, s2, off);
    }
    if (tid == 0) {
        const double N = (double)(T_SEQ * HD);
        double mu  = s / N;
        double var = s2 / N - mu * mu;
        g_MU[bh] = (float)mu;
        g_RS[bh] = (float)rsqrt(var + 1e-5);
    }
}

__global__ __launch_bounds__(256) void gn_apply(
    const float* __restrict__ O, const float* __restrict__ gw,
    const float* __restrict__ gb, char* __restrict__ YP)
{
    const int f = blockIdx.x * 256 + threadIdx.x;
    const int bh = f >> 15;
    const int rem = f & 32767;
    const int t = rem >> 4;
    const int d4 = (rem & 15) * 4;
    const int b = bh >> 4, h = bh & 15;

    const float mu = g_MU[bh], rs = g_RS[bh];
    float4 v = *(const float4*)(O + ((size_t)bh * T_SEQ + t) * HD + d4);
    float4 w = *(const float4*)(gw + h * HD + d4);
    float4 bb = *(const float4*)(gb + h * HD + d4);
    float r[4];
    r[0] = (v.x - mu) * rs * w.x + bb.x;
    r[1] = (v.y - mu) * rs * w.y + bb.y;
    r[2] = (v.z - mu) * rs * w.z + bb.z;
    r[3] = (v.w - mu) * rs * w.w + bb.w;

    unsigned hu[2], lu[2];
    split2(r[0], r[1], hu[0], lu[0]);
    split2(r[2], r[3], hu[1], lu[1]);
    const int m = b * T_SEQ + t;
    const int k0 = h * HD + d4;
    char* dst = YP + PK(m >> 7, k0 >> 5) + (m & 127) * (ARS * 2) + (k0 & 31) * 2;
    uint2 hv = {hu[0], hu[1]};
    uint2 lv = {lu[0], lu[1]};
    *(uint2*)dst = hv;
    *(uint2*)(dst + MATB) = lv;
}

// ---------------------------------------------------------------------------
extern "C" void kernel_launch(void* const* d_in, const int* in_sizes, int n_in,
                              void* d_out, int out_size)
{
    const float* x   = (const float*)d_in[0];
    const float* Wq  = (const float*)d_in[1];
    const float* Wk  = (const float*)d_in[2];
    const float* Wv  = (const float*)d_in[3];
    const float* Wo  = (const float*)d_in[4];
    const float* gnw = (const float*)d_in[5];
    const float* gnb = (const float*)d_in[6];
    float* out = (float*)d_out;

    float *qkv, *o, *gg, *ss;
    char *xp, *wp, *yp;
    cudaGetSymbolAddress((void**)&qkv, g_QKV);
    cudaGetSymbolAddress((void**)&o, g_O);
    cudaGetSymbolAddress((void**)&gg, g_G);
    cudaGetSymbolAddress((void**)&ss, g_S);
    cudaGetSymbolAddress((void**)&xp, g_XP);
    cudaGetSymbolAddress((void**)&wp, g_WP);
    cudaGetSymbolAddress((void**)&yp, g_YP);

    float* q = qkv;
    float* k = qkv + 1 * (size_t)BH * T_SEQ * HD;
    float* v = qkv + 2 * (size_t)BH * T_SEQ * HD;

    const int gemm_smem = 128 + NSTG * STGB;
    cudaFuncSetAttribute(gemm_mma, cudaFuncAttributeMaxDynamicSharedMemorySize, gemm_smem);
    cudaFuncSetAttribute(retention_chunk, cudaFuncAttributeMaxDynamicSharedMemorySize, 81920);

    pack_split<<<2048, 256>>>(x, xp, 0);
    pack_w4<<<2048, 256>>>(Wq, Wk, Wv, Wo, wp);

    dim3 gQKV(3 * DM / 128, MROWS / 128);   // (24, 32)
    gemm_mma<<<gQKV, 256, gemm_smem>>>(xp, wp, qkv, 3 * DM, 1);

    chunk_state<<<dim3(NCH, BH), 256>>>(k, v, gg);
    state_scan<<<BH, 256>>>(gg, ss);
    retention_chunk<<<dim3(NCH, BH), 256, 81920>>>(q, k, v, ss, o);

    gn_finalize<<<BH, 32>>>();
    gn_apply<<<(MROWS * DM) / (4 * 256), 256>>>(o, gnw, gnb, yp);

    dim3 gO(DM / 128, MROWS / 128);         // (8, 32)
    gemm_mma<<<gO, 256, gemm_smem>>>(yp, wp + (size_t)24 * NBK * PAIRB, out, DM, 0);
}

// round 11
// speedup vs baseline: 1.1779x; 1.1145x over previous
#include <cuda_runtime.h>
#include <cuda_bf16.h>
#include <cuda_fp16.h>
#include <math.h>

#define T_SEQ   2048
#define NH      16
#define HD      64
#define DM      1024
#define BATCH   2
#define MROWS   (BATCH * T_SEQ)   // 4096
#define L_CH    64
#define NCH     (T_SEQ / L_CH)    // 32
#define BH      (BATCH * NH)      // 32

// GEMM tiling
#define KC 32
#define ARS 40                      // padded row stride in fp16 (80 B)
#define MATB (128 * ARS * 2)        // 10240 B per matrix image
#define PAIRB (2 * MATB)            // 20480 B = hi|lo pair (A side: x / y)
#define STGB (PAIRB + MATB)         // 30720 B per stage (Ahi|Alo|B)
#define NSTG 4
#define NBK  (DM / KC)              // 32 k-chunks
#define PKA(t, c) (((size_t)(t) * NBK + (c)) * PAIRB)
#define PKB(t, c) (((size_t)(t) * NBK + (c)) * MATB)

// ---------------------------------------------------------------------------
// Scratch (device globals: allocation-free per harness rules)
// ---------------------------------------------------------------------------
__device__ __align__(16) float g_QKV[3 * (size_t)BH * T_SEQ * HD];
__device__ __align__(16) float g_O[(size_t)BH * T_SEQ * HD];
__device__ __align__(16) float g_G[(size_t)BH * NCH * HD * HD];
__device__ __align__(16) float g_S[(size_t)BH * NCH * HD * HD];
__device__ double g_PS[BH * NCH];
__device__ double g_PS2[BH * NCH];
__device__ float g_MU[BH];
__device__ float g_RS[BH];

__device__ __align__(128) char g_XP[(size_t)32 * NBK * PAIRB];   // x  (hi|lo fp16)
__device__ __align__(128) char g_WP[(size_t)32 * NBK * MATB];    // Wq|Wk|Wv|Wo (single fp16)
__device__ __align__(128) char g_YP[(size_t)32 * NBK * PAIRB];   // gn out (hi|lo fp16)

// ---------------------------------------------------------------------------
// Baseline-PTX helpers
// ---------------------------------------------------------------------------
__device__ __forceinline__ unsigned smem_u32(const void* p) {
    unsigned a;
    asm("{ .reg .u64 t; cvta.to.shared.u64 t, %1; cvt.u32.u64 %0, t; }"
        : "=r"(a) : "l"(p));
    return a;
}
__device__ __forceinline__ void ldsm_x4(unsigned* r, unsigned addr) {
    asm volatile("ldmatrix.sync.aligned.m8n8.x4.shared.b16 {%0,%1,%2,%3}, [%4];"
                 : "=r"(r[0]), "=r"(r[1]), "=r"(r[2]), "=r"(r[3]) : "r"(addr));
}
__device__ __forceinline__ void mma_f16(float* d, const unsigned* a, const unsigned* b) {
    asm volatile(
        "mma.sync.aligned.m16n8k16.row.col.f32.f16.f16.f32 "
        "{%0,%1,%2,%3}, {%4,%5,%6,%7}, {%8,%9}, {%0,%1,%2,%3};"
        : "+f"(d[0]), "+f"(d[1]), "+f"(d[2]), "+f"(d[3])
        : "r"(a[0]), "r"(a[1]), "r"(a[2]), "r"(a[3]), "r"(b[0]), "r"(b[1]));
}

#define MBAR_INIT(sa, n) \
    asm volatile("mbarrier.init.shared.b64 [%0], %1;" :: "r"((unsigned)(sa)), "r"((unsigned)(n)) : "memory")
#define MBAR_EXPECT(sa, bytes) \
    asm volatile("mbarrier.arrive.expect_tx.shared.b64 _, [%0], %1;" \
                 :: "r"((unsigned)(sa)), "r"((unsigned)(bytes)) : "memory")
#define CP_BULK(dst, src, nbytes, mbar) \
    asm volatile("cp.async.bulk.shared::cluster.global.mbarrier::complete_tx::bytes [%0], [%1], %2, [%3];" \
                 :: "r"((unsigned)(dst)), "l"(src), "r"((unsigned)(nbytes)), "r"((unsigned)(mbar)) : "memory")

#define MBAR_WAIT(sa, ph) do {                                                  \
    unsigned _m = (unsigned)(sa), _p = (unsigned)(ph), _d;                      \
    asm volatile(                                                               \
        "{\n\t.reg .pred p;\n\t"                                                \
        "mbarrier.try_wait.parity.acquire.cta.shared::cta.b64 p, [%1], %2;\n\t" \
        "selp.b32 %0, 1, 0, p;\n\t}"                                            \
        : "=r"(_d) : "r"(_m), "r"(_p) : "memory");                              \
    if (!_d) {                                                                  \
        asm volatile(                                                           \
            "{\n\t.reg .pred P1;\n\t"                                           \
            "WL_%=:\n\t"                                                        \
            "mbarrier.try_wait.parity.acquire.cta.shared::cta.b64 P1, [%0], %1, 0x989680;\n\t" \
            "@P1 bra.uni WD_%=;\n\t"                                            \
            "bra.uni WL_%=;\n\t"                                                \
            "WD_%=:\n\t}"                                                       \
            :: "r"(_m), "r"(_p) : "memory");                                    \
    }                                                                           \
} while (0)

// fp16 splits
__device__ __forceinline__ void split2h(float x0, float x1, unsigned& hu, unsigned& lu) {
    __half h0 = __float2half_rn(x0), h1 = __float2half_rn(x1);
    __half l0 = __float2half_rn(x0 - __half2float(h0));
    __half l1 = __float2half_rn(x1 - __half2float(h1));
    hu = (unsigned)__half_as_ushort(h0) | ((unsigned)__half_as_ushort(h1) << 16);
    lu = (unsigned)__half_as_ushort(l0) | ((unsigned)__half_as_ushort(l1) << 16);
}
__device__ __forceinline__ void split8h(const float* v, uint4& hv, uint4& lv) {
    unsigned hu[4], lu[4];
#pragma unroll
    for (int j = 0; j < 4; j++) split2h(v[2 * j], v[2 * j + 1], hu[j], lu[j]);
    hv = make_uint4(hu[0], hu[1], hu[2], hu[3]);
    lv = make_uint4(lu[0], lu[1], lu[2], lu[3]);
}
__device__ __forceinline__ uint4 cvt8h(const float* v) {
    unsigned u[4];
#pragma unroll
    for (int j = 0; j < 4; j++) {
        __half h0 = __float2half_rn(v[2 * j]), h1 = __float2half_rn(v[2 * j + 1]);
        u[j] = (unsigned)__half_as_ushort(h0) | ((unsigned)__half_as_ushort(h1) << 16);
    }
    return make_uint4(u[0], u[1], u[2], u[3]);
}

// ---------------------------------------------------------------------------
// Packers
// ---------------------------------------------------------------------------
// x -> hi/lo fp16 pair images
__global__ __launch_bounds__(256) void pack_split(
    const float* __restrict__ X, char* __restrict__ P)
{
    const int gid = blockIdx.x * 256 + threadIdx.x;
    const int m   = gid >> 7;
    const int rem = gid & 127;
    const int c   = rem >> 2;
    const int c16 = rem & 3;
    const float* src = X + (size_t)m * DM + c * KC + c16 * 8;
    float v[8];
    float4 a = *(const float4*)src;
    float4 b = *(const float4*)(src + 4);
    v[0] = a.x; v[1] = a.y; v[2] = a.z; v[3] = a.w;
    v[4] = b.x; v[5] = b.y; v[6] = b.z; v[7] = b.w;
    uint4 hv, lv;
    split8h(v, hv, lv);
    char* dst = P + PKA((m >> 7), c) + (m & 127) * (ARS * 2) + c16 * 16;
    *(uint4*)dst = hv;
    *(uint4*)(dst + MATB) = lv;
}

// all four weights -> single fp16 images, one launch (grid 2048)
__global__ __launch_bounds__(256) void pack_w4(
    const float* __restrict__ W0, const float* __restrict__ W1,
    const float* __restrict__ W2, const float* __restrict__ W3,
    char* __restrict__ P)
{
    const int gid = blockIdx.x * 256 + threadIdx.x;   // 0..524287
    const int wsel = gid >> 17;
    const int g = gid & 131071;
    const float* W = (wsel == 0) ? W0 : (wsel == 1) ? W1 : (wsel == 2) ? W2 : W3;
    const int m   = g >> 7;
    const int rem = g & 127;
    const int c   = rem >> 2;
    const int c16 = rem & 3;
    const float* src = W + (size_t)m * DM + c * KC + c16 * 8;
    float v[8];
    float4 a = *(const float4*)src;
    float4 b = *(const float4*)(src + 4);
    v[0] = a.x; v[1] = a.y; v[2] = a.z; v[3] = a.w;
    v[4] = b.x; v[5] = b.y; v[6] = b.z; v[7] = b.w;
    uint4 hv = cvt8h(v);
    char* dst = P + PKB(wsel * 8 + (m >> 7), c) + (m & 127) * (ARS * 2) + c16 * 16;
    *(uint4*)dst = hv;
}

// ---------------------------------------------------------------------------
// mma.sync GEMM: A = 2-term fp16 (hi|lo), B = single fp16 -> 2 MMA terms.
// Block 128x128, 8 warps (wm 2 x wn 4), cp.async.bulk, 4-stage.
// layout 0: C row-major MxN. layout 1: QKV scatter (n>>10 selects Q/K/V).
// ---------------------------------------------------------------------------
__global__ __launch_bounds__(256) void gemm_mma(
    const char* __restrict__ Ap, const char* __restrict__ Bp,
    float* __restrict__ C, int N, int layout)
{
    extern __shared__ char smc[];
    const unsigned sb = smem_u32(smc);
    const unsigned sdata = sb + 128;
    const int tid = threadIdx.x;
    const int wid = tid >> 5;
    const int lane = tid & 31;
    const int bm = blockIdx.y, bn = blockIdx.x;
    const int wm = wid & 1;
    const int wn = wid >> 1;

    if (tid == 0) {
        MBAR_INIT(sb + 0, 1);
        MBAR_INIT(sb + 8, 1);
        MBAR_INIT(sb + 16, 1);
        MBAR_INIT(sb + 24, 1);
    }
    __syncthreads();

    auto issue = [&](int c, int s) {
        unsigned mb = sb + s * 8;
        MBAR_EXPECT(mb, STGB);
        unsigned dst = sdata + s * STGB;
        CP_BULK(dst,         Ap + PKA(bm, c), PAIRB, mb);
        CP_BULK(dst + PAIRB, Bp + PKB(bn, c), MATB, mb);
    };

    if (tid == 0) { issue(0, 0); issue(1, 1); issue(2, 2); }

    float d[16][4];
#pragma unroll
    for (int f = 0; f < 16; f++)
#pragma unroll
        for (int j = 0; j < 4; j++) d[f][j] = 0.f;

    for (int c = 0; c < NBK; c++) {
        const int s = c % NSTG;
        MBAR_WAIT(sb + s * 8, (c / NSTG) & 1);

        const unsigned base = sdata + s * STGB;
#pragma unroll
        for (int kk = 0; kk < KC; kk += 16) {
            unsigned Ahf[4][4], Alf[4][4];
#pragma unroll
            for (int fm = 0; fm < 4; fm++) {
                unsigned row = wm * 64 + fm * 16 + (lane & 15);
                unsigned col = kk + (lane >> 4) * 8;
                unsigned addr = base + row * (ARS * 2) + col * 2;
                ldsm_x4(Ahf[fm], addr);
                ldsm_x4(Alf[fm], addr + MATB);
            }
            unsigned Bf[4][2];
#pragma unroll
            for (int fnp = 0; fnp < 2; fnp++) {
                unsigned row = wn * 32 + fnp * 16 + (lane & 15);
                unsigned col = kk + (lane >> 4) * 8;
                unsigned addr = base + PAIRB + row * (ARS * 2) + col * 2;
                unsigned bH[4];
                ldsm_x4(bH, addr);
                Bf[2 * fnp][0] = bH[0]; Bf[2 * fnp][1] = bH[2];
                Bf[2 * fnp + 1][0] = bH[1]; Bf[2 * fnp + 1][1] = bH[3];
            }
#pragma unroll
            for (int fm = 0; fm < 4; fm++)
#pragma unroll
                for (int fn = 0; fn < 4; fn++) {
                    float* acc = d[fm * 4 + fn];
                    mma_f16(acc, Ahf[fm], Bf[fn]);
                    mma_f16(acc, Alf[fm], Bf[fn]);
                }
        }
        __syncthreads();
        if (tid == 0 && c + 3 < NBK) issue(c + 3, (c + 3) % NSTG);
    }

    const int mloc0 = bm * 128 + wm * 64 + (lane >> 2);
    const int nloc0 = bn * 128 + wn * 32 + (lane & 3) * 2;
#pragma unroll
    for (int fm = 0; fm < 4; fm++) {
#pragma unroll
        for (int fn = 0; fn < 4; fn++) {
            const float* acc = d[fm * 4 + fn];
            const int n = nloc0 + fn * 8;
#pragma unroll
            for (int rr = 0; rr < 2; rr++) {
                const int m = mloc0 + fm * 16 + rr * 8;
                float2 v = {acc[rr * 2], acc[rr * 2 + 1]};
                if (layout == 0) {
                    *(float2*)(C + (size_t)m * N + n) = v;
                } else {
                    const int which = n >> 10;
                    const int nn = n & 1023;
                    const int h = nn >> 6, dd = nn & 63;
                    const int bb = m >> 11, t = m & 2047;
                    float* dst = C + (size_t)which * (BH * T_SEQ * HD)
                               + (((size_t)(bb * NH + h) * T_SEQ + t) * HD + dd);
                    *(float2*)dst = v;
                }
            }
        }
    }
}

// ---------------------------------------------------------------------------
// Pass A: G_c[d1][d2] = sum_b gamma^(L-b) K[b][d1] V[b][d2]
// ---------------------------------------------------------------------------
__global__ __launch_bounds__(256) void chunk_state(
    const float* __restrict__ K, const float* __restrict__ V,
    float* __restrict__ G)
{
    __shared__ __align__(16) float Ks[L_CH][HD];
    __shared__ __align__(16) float Vs[L_CH][HD];

    const int c  = blockIdx.x;
    const int bh = blockIdx.y;
    const int h  = bh & (NH - 1);
    const int tid = threadIdx.x;
    const int rB = (tid >> 4) * 4;
    const int cB = (tid & 15) * 4;

    const double g_d = 1.0 - exp2(-5.0 - 0.5 * (double)h);
    const float lg = (float)log2(g_d);

    const float* Kg = K + ((size_t)bh * T_SEQ + c * L_CH) * HD;
    const float* Vg = V + ((size_t)bh * T_SEQ + c * L_CH) * HD;
#pragma unroll
    for (int u = 0; u < 4; u++) {
        int idx = tid + u * 256;
        int t = idx >> 4;
        int d4 = (idx & 15) * 4;
        float w = exp2f((float)(L_CH - t) * lg);
        float4 kv = *(const float4*)(Kg + t * HD + d4);
        kv.x *= w; kv.y *= w; kv.z *= w; kv.w *= w;
        *(float4*)&Ks[t][d4] = kv;
        *(float4*)&Vs[t][d4] = *(const float4*)(Vg + t * HD + d4);
    }
    __syncthreads();

    float acc[4][4];
#pragma unroll
    for (int i = 0; i < 4; i++)
#pragma unroll
        for (int j = 0; j < 4; j++) acc[i][j] = 0.f;

#pragma unroll 4
    for (int k = 0; k < L_CH; k++) {
        float4 ak = *(const float4*)&Ks[k][rB];
        float4 bk = *(const float4*)&Vs[k][cB];
        float ar[4] = {ak.x, ak.y, ak.z, ak.w};
#pragma unroll
        for (int i = 0; i < 4; i++) {
            acc[i][0] += ar[i] * bk.x; acc[i][1] += ar[i] * bk.y;
            acc[i][2] += ar[i] * bk.z; acc[i][3] += ar[i] * bk.w;
        }
    }

    float* Gg = G + ((size_t)bh * NCH + c) * HD * HD;
#pragma unroll
    for (int i = 0; i < 4; i++) {
        float4 v = {acc[i][0], acc[i][1], acc[i][2], acc[i][3]};
        *(float4*)&Gg[(rB + i) * HD + cB] = v;
    }
}

// ---------------------------------------------------------------------------
// Pass B: S_0 = 0 ; S_c = gamma^L * S_{c-1} + G_{c-1}
// ---------------------------------------------------------------------------
__global__ __launch_bounds__(256) void state_scan(
    const float* __restrict__ G, float* __restrict__ S)
{
    const int bh = blockIdx.x;
    const int h  = bh & (NH - 1);
    const int tid = threadIdx.x;
    const double g_d = 1.0 - exp2(-5.0 - 0.5 * (double)h);
    const float decL = (float)exp2((double)L_CH * log2(g_d));

    const size_t base = (size_t)bh * NCH * HD * HD;
    float s[16];
#pragma unroll
    for (int u = 0; u < 16; u++) s[u] = 0.f;

    for (int c = 0; c < NCH; c++) {
        const size_t off = base + (size_t)c * HD * HD;
#pragma unroll
        for (int u = 0; u < 16; u++) {
            int e = tid + u * 256;
            S[off + e] = s[u];
            s[u] = s[u] * decL + G[off + e];
        }
    }
}

// ---------------------------------------------------------------------------
// Pass C: O = gamma^a * (Q/8) @ S_c + intra-chunk decayed quadratic
// + fused GN partial reduction per block.
// ---------------------------------------------------------------------------
__global__ __launch_bounds__(256) void retention_chunk(
    const float* __restrict__ Q, const float* __restrict__ K,
    const float* __restrict__ V, const float* __restrict__ S,
    float* __restrict__ O)
{
    extern __shared__ __align__(16) float sm[];
    float* Qs = sm;
    float* Kt = sm + 4096;
    float* Vs = sm + 8192;
    float* Ss = sm + 12288;
    float* St = sm + 16384;

    const int c  = blockIdx.x;
    const int bh = blockIdx.y;
    const int h  = bh & (NH - 1);
    const int r0 = c * L_CH;
    const int tid = threadIdx.x;
    const int rB = (tid >> 4) * 4;
    const int cB = (tid & 15) * 4;

    const double g_d = 1.0 - exp2(-5.0 - 0.5 * (double)h);
    const float lg = (float)log2(g_d);

    const float* Qg = Q + ((size_t)bh * T_SEQ + r0) * HD;
    const float* Kg = K + ((size_t)bh * T_SEQ + r0) * HD;
    const float* Vg = V + ((size_t)bh * T_SEQ + r0) * HD;
    const float* Sg = S + ((size_t)bh * NCH + c) * HD * HD;

#pragma unroll
    for (int u = 0; u < 4; u++) {
        int idx = tid + u * 256;
        int t = idx >> 4;
        int d4 = (idx & 15) * 4;
        *(float4*)&Qs[t * 64 + d4] = *(const float4*)(Qg + t * HD + d4);
        float4 kv = *(const float4*)(Kg + t * HD + d4);
        Kt[(d4 + 0) * 64 + t] = kv.x;
        Kt[(d4 + 1) * 64 + t] = kv.y;
        Kt[(d4 + 2) * 64 + t] = kv.z;
        Kt[(d4 + 3) * 64 + t] = kv.w;
        *(float4*)&Vs[t * 64 + d4] = *(const float4*)(Vg + t * HD + d4);
        *(float4*)&St[t * 64 + d4] = *(const float4*)(Sg + t * HD + d4);
    }
    __syncthreads();

    float acc[4][4];
#pragma unroll
    for (int i = 0; i < 4; i++)
#pragma unroll
        for (int j = 0; j < 4; j++) acc[i][j] = 0.f;

#pragma unroll 4
    for (int k = 0; k < HD; k++) {
        float a0 = Qs[(rB + 0) * 64 + k];
        float a1 = Qs[(rB + 1) * 64 + k];
        float a2 = Qs[(rB + 2) * 64 + k];
        float a3 = Qs[(rB + 3) * 64 + k];
        float4 bq = *(const float4*)&St[k * 64 + cB];
        acc[0][0] += a0 * bq.x; acc[0][1] += a0 * bq.y; acc[0][2] += a0 * bq.z; acc[0][3] += a0 * bq.w;
        acc[1][0] += a1 * bq.x; acc[1][1] += a1 * bq.y; acc[1][2] += a1 * bq.z; acc[1][3] += a1 * bq.w;
        acc[2][0] += a2 * bq.x; acc[2][1] += a2 * bq.y; acc[2][2] += a2 * bq.z; acc[2][3] += a2 * bq.w;
        acc[3][0] += a3 * bq.x; acc[3][1] += a3 * bq.y; acc[3][2] += a3 * bq.z; acc[3][3] += a3 * bq.w;
    }
#pragma unroll
    for (int i = 0; i < 4; i++) {
        float f = exp2f((float)(rB + i) * lg) * 0.125f;
#pragma unroll
        for (int j = 0; j < 4; j++) acc[i][j] *= f;
    }

    float s[4][4];
#pragma unroll
    for (int i = 0; i < 4; i++)
#pragma unroll
        for (int j = 0; j < 4; j++) s[i][j] = 0.f;

#pragma unroll 4
    for (int k = 0; k < HD; k++) {
        float a0 = Qs[(rB + 0) * 64 + k];
        float a1 = Qs[(rB + 1) * 64 + k];
        float a2 = Qs[(rB + 2) * 64 + k];
        float a3 = Qs[(rB + 3) * 64 + k];
        float4 bq = *(const float4*)&Kt[k * 64 + cB];
        s[0][0] += a0 * bq.x; s[0][1] += a0 * bq.y; s[0][2] += a0 * bq.z; s[0][3] += a0 * bq.w;
        s[1][0] += a1 * bq.x; s[1][1] += a1 * bq.y; s[1][2] += a1 * bq.z; s[1][3] += a1 * bq.w;
        s[2][0] += a2 * bq.x; s[2][1] += a2 * bq.y; s[2][2] += a2 * bq.z; s[2][3] += a2 * bq.w;
        s[3][0] += a3 * bq.x; s[3][1] += a3 * bq.y; s[3][2] += a3 * bq.z; s[3][3] += a3 * bq.w;
    }

#pragma unroll
    for (int i = 0; i < 4; i++) {
#pragma unroll
        for (int j = 0; j < 4; j++) {
            int di = (rB + i) - (cB + j);
            float dec = (di >= 0) ? exp2f((float)di * lg) : 0.f;
            Ss[(rB + i) * 64 + (cB + j)] = s[i][j] * 0.125f * dec;
        }
    }
    __syncthreads();

#pragma unroll 4
    for (int k = 0; k < L_CH; k++) {
        float a0 = Ss[(rB + 0) * 64 + k];
        float a1 = Ss[(rB + 1) * 64 + k];
        float a2 = Ss[(rB + 2) * 64 + k];
        float a3 = Ss[(rB + 3) * 64 + k];
        float4 bv = *(const float4*)&Vs[k * 64 + cB];
        acc[0][0] += a0 * bv.x; acc[0][1] += a0 * bv.y; acc[0][2] += a0 * bv.z; acc[0][3] += a0 * bv.w;
        acc[1][0] += a1 * bv.x; acc[1][1] += a1 * bv.y; acc[1][2] += a1 * bv.z; acc[1][3] += a1 * bv.w;
        acc[2][0] += a2 * bv.x; acc[2][1] += a2 * bv.y; acc[2][2] += a2 * bv.z; acc[2][3] += a2 * bv.w;
        acc[3][0] += a3 * bv.x; acc[3][1] += a3 * bv.y; acc[3][2] += a3 * bv.z; acc[3][3] += a3 * bv.w;
    }

    float* Og = O + ((size_t)bh * T_SEQ + r0) * HD;
#pragma unroll
    for (int i = 0; i < 4; i++) {
        float4 v = {acc[i][0], acc[i][1], acc[i][2], acc[i][3]};
        *(float4*)&Og[(rB + i) * 64 + cB] = v;
    }

    // fused GN partial
    double ds = 0.0, ds2 = 0.0;
#pragma unroll
    for (int i = 0; i < 4; i++)
#pragma unroll
        for (int j = 0; j < 4; j++) {
            double x = (double)acc[i][j];
            ds += x; ds2 += x * x;
        }
    __syncthreads();
    double* shd  = (double*)sm;
    double* shd2 = (double*)sm + 256;
    shd[tid] = ds; shd2[tid] = ds2;
    __syncthreads();
    for (int off = 128; off > 0; off >>= 1) {
        if (tid < off) { shd[tid] += shd[tid + off]; shd2[tid] += shd2[tid + off]; }
        __syncthreads();
    }
    if (tid == 0) {
        g_PS[bh * NCH + c]  = shd[0];
        g_PS2[bh * NCH + c] = shd2[0];
    }
}

// ---------------------------------------------------------------------------
// GroupNorm finalize + apply (writes packed y tiles, fp16 hi/lo)
// ---------------------------------------------------------------------------
__global__ void gn_finalize()
{
    const int bh = blockIdx.x;
    const int tid = threadIdx.x;   // 32 threads
    double s  = g_PS[bh * NCH + tid];
    double s2 = g_PS2[bh * NCH + tid];
#pragma unroll
    for (int off = 16; off > 0; off >>= 1) {
        s  += __shfl_down_sync(0xffffffff, s,  off);
        s2 += __shfl_down_sync(0xffffffff, s2, off);
    }
    if (tid == 0) {
        const double N = (double)(T_SEQ * HD);
        double mu  = s / N;
        double var = s2 / N - mu * mu;
        g_MU[bh] = (float)mu;
        g_RS[bh] = (float)rsqrt(var + 1e-5);
    }
}

__global__ __launch_bounds__(256) void gn_apply(
    const float* __restrict__ O, const float* __restrict__ gw,
    const float* __restrict__ gb, char* __restrict__ YP)
{
    const int f = blockIdx.x * 256 + threadIdx.x;
    const int bh = f >> 15;
    const int rem = f & 32767;
    const int t = rem >> 4;
    const int d4 = (rem & 15) * 4;
    const int b = bh >> 4, h = bh & 15;

    const float mu = g_MU[bh], rs = g_RS[bh];
    float4 v = *(const float4*)(O + ((size_t)bh * T_SEQ + t) * HD + d4);
    float4 w = *(const float4*)(gw + h * HD + d4);
    float4 bb = *(const float4*)(gb + h * HD + d4);
    float r[4];
    r[0] = (v.x - mu) * rs * w.x + bb.x;
    r[1] = (v.y - mu) * rs * w.y + bb.y;
    r[2] = (v.z - mu) * rs * w.z + bb.z;
    r[3] = (v.w - mu) * rs * w.w + bb.w;

    unsigned hu[2], lu[2];
    split2h(r[0], r[1], hu[0], lu[0]);
    split2h(r[2], r[3], hu[1], lu[1]);
    const int m = b * T_SEQ + t;
    const int k0 = h * HD + d4;
    char* dst = YP + PKA(m >> 7, k0 >> 5) + (m & 127) * (ARS * 2) + (k0 & 31) * 2;
    uint2 hv = {hu[0], hu[1]};
    uint2 lv = {lu[0], lu[1]};
    *(uint2*)dst = hv;
    *(uint2*)(dst + MATB) = lv;
}

// ---------------------------------------------------------------------------
extern "C" void kernel_launch(void* const* d_in, const int* in_sizes, int n_in,
                              void* d_out, int out_size)
{
    const float* x   = (const float*)d_in[0];
    const float* Wq  = (const float*)d_in[1];
    const float* Wk  = (const float*)d_in[2];
    const float* Wv  = (const float*)d_in[3];
    const float* Wo  = (const float*)d_in[4];
    const float* gnw = (const float*)d_in[5];
    const float* gnb = (const float*)d_in[6];
    float* out = (float*)d_out;

    float *qkv, *o, *gg, *ss;
    char *xp, *wp, *yp;
    cudaGetSymbolAddress((void**)&qkv, g_QKV);
    cudaGetSymbolAddress((void**)&o, g_O);
    cudaGetSymbolAddress((void**)&gg, g_G);
    cudaGetSymbolAddress((void**)&ss, g_S);
    cudaGetSymbolAddress((void**)&xp, g_XP);
    cudaGetSymbolAddress((void**)&wp, g_WP);
    cudaGetSymbolAddress((void**)&yp, g_YP);

    float* q = qkv;
    float* k = qkv + 1 * (size_t)BH * T_SEQ * HD;
    float* v = qkv + 2 * (size_t)BH * T_SEQ * HD;

    const int gemm_smem = 128 + NSTG * STGB;   // 123008
    cudaFuncSetAttribute(gemm_mma, cudaFuncAttributeMaxDynamicSharedMemorySize, gemm_smem);
    cudaFuncSetAttribute(retention_chunk, cudaFuncAttributeMaxDynamicSharedMemorySize, 81920);

    pack_split<<<2048, 256>>>(x, xp);
    pack_w4<<<2048, 256>>>(Wq, Wk, Wv, Wo, wp);

    dim3 gQKV(3 * DM / 128, MROWS / 128);   // (24, 32)
    gemm_mma<<<gQKV, 256, gemm_smem>>>(xp, wp, qkv, 3 * DM, 1);

    chunk_state<<<dim3(NCH, BH), 256>>>(k, v, gg);
    state_scan<<<BH, 256>>>(gg, ss);
    retention_chunk<<<dim3(NCH, BH), 256, 81920>>>(q, k, v, ss, o);

    gn_finalize<<<BH, 32>>>();
    gn_apply<<<(MROWS * DM) / (4 * 256), 256>>>(o, gnw, gnb, yp);

    dim3 gO(DM / 128, MROWS / 128);         // (8, 32)
    gemm_mma<<<gO, 256, gemm_smem>>>(yp, wp + PKB(24, 0), out, DM, 0);
}

// round 13
// speedup vs baseline: 1.2071x; 1.0248x over previous
#include <cuda_runtime.h>
#include <cuda_bf16.h>
#include <cuda_fp16.h>
#include <math.h>

#define T_SEQ   2048
#define NH      16
#define HD      64
#define DM      1024
#define BATCH   2
#define MROWS   (BATCH * T_SEQ)   // 4096
#define L_CH    64
#define NCH     (T_SEQ / L_CH)    // 32
#define BH      (BATCH * NH)      // 32

// GEMM tiling
#define KC 32
#define ARS 40                      // padded row stride in fp16 (80 B)
#define MATB (128 * ARS * 2)        // 10240 B per matrix image
#define PAIRB (2 * MATB)            // 20480 B = hi|lo pair (A side)
#define STGB (PAIRB + MATB)         // 30720 B per stage (Ahi|Alo|B)
#define NSTG 4
#define NBK  (DM / KC)              // 32 k-chunks
#define PKA(t, c) (((size_t)(t) * NBK + (c)) * PAIRB)
#define PKB(t, c) (((size_t)(t) * NBK + (c)) * MATB)

// ---------------------------------------------------------------------------
// Scratch (device globals: allocation-free per harness rules)
// ---------------------------------------------------------------------------
__device__ __align__(16) float g_QKV[3 * (size_t)BH * T_SEQ * HD];
__device__ __align__(16) float g_O[(size_t)BH * T_SEQ * HD];
__device__ __align__(16) float g_G[(size_t)BH * NCH * HD * HD];
__device__ __align__(16) float g_S[(size_t)BH * NCH * HD * HD];
__device__ double g_PS[BH * NCH];
__device__ double g_PS2[BH * NCH];
__device__ float g_MU[BH];
__device__ float g_RS[BH];

__device__ __align__(128) char g_XP[(size_t)32 * NBK * PAIRB];   // x  (hi|lo fp16)
__device__ __align__(128) char g_WP[(size_t)32 * NBK * MATB];    // Wq|Wk|Wv|Wo (fp16)
__device__ __align__(128) char g_YP[(size_t)32 * NBK * PAIRB];   // gn out (hi|lo fp16)

// ---------------------------------------------------------------------------
// Baseline-PTX helpers
// ---------------------------------------------------------------------------
__device__ __forceinline__ unsigned smem_u32(const void* p) {
    unsigned a;
    asm("{ .reg .u64 t; cvta.to.shared.u64 t, %1; cvt.u32.u64 %0, t; }"
        : "=r"(a) : "l"(p));
    return a;
}
__device__ __forceinline__ void ldsm_x4(unsigned* r, unsigned addr) {
    asm volatile("ldmatrix.sync.aligned.m8n8.x4.shared.b16 {%0,%1,%2,%3}, [%4];"
                 : "=r"(r[0]), "=r"(r[1]), "=r"(r[2]), "=r"(r[3]) : "r"(addr));
}
__device__ __forceinline__ void mma_f16(float* d, const unsigned* a, const unsigned* b) {
    asm volatile(
        "mma.sync.aligned.m16n8k16.row.col.f32.f16.f16.f32 "
        "{%0,%1,%2,%3}, {%4,%5,%6,%7}, {%8,%9}, {%0,%1,%2,%3};"
        : "+f"(d[0]), "+f"(d[1]), "+f"(d[2]), "+f"(d[3])
        : "r"(a[0]), "r"(a[1]), "r"(a[2]), "r"(a[3]), "r"(b[0]), "r"(b[1]));
}

#define MBAR_INIT(sa, n) \
    asm volatile("mbarrier.init.shared.b64 [%0], %1;" :: "r"((unsigned)(sa)), "r"((unsigned)(n)) : "memory")
#define MBAR_EXPECT(sa, bytes) \
    asm volatile("mbarrier.arrive.expect_tx.shared.b64 _, [%0], %1;" \
                 :: "r"((unsigned)(sa)), "r"((unsigned)(bytes)) : "memory")
#define CP_BULK(dst, src, nbytes, mbar) \
    asm volatile("cp.async.bulk.shared::cluster.global.mbarrier::complete_tx::bytes [%0], [%1], %2, [%3];" \
                 :: "r"((unsigned)(dst)), "l"(src), "r"((unsigned)(nbytes)), "r"((unsigned)(mbar)) : "memory")

#define MBAR_WAIT(sa, ph) do {                                                  \
    unsigned _m = (unsigned)(sa), _p = (unsigned)(ph), _d;                      \
    asm volatile(                                                               \
        "{\n\t.reg .pred p;\n\t"                                                \
        "mbarrier.try_wait.parity.acquire.cta.shared::cta.b64 p, [%1], %2;\n\t" \
        "selp.b32 %0, 1, 0, p;\n\t}"                                            \
        : "=r"(_d) : "r"(_m), "r"(_p) : "memory");                              \
    if (!_d) {                                                                  \
        asm volatile(                                                           \
            "{\n\t.reg .pred P1;\n\t"                                           \
            "WL_%=:\n\t"                                                        \
            "mbarrier.try_wait.parity.acquire.cta.shared::cta.b64 P1, [%0], %1, 0x989680;\n\t" \
            "@P1 bra.uni WD_%=;\n\t"                                            \
            "bra.uni WL_%=;\n\t"                                                \
            "WD_%=:\n\t}"                                                       \
            :: "r"(_m), "r"(_p) : "memory");                                    \
    }                                                                           \
} while (0)

// fp16 splits
__device__ __forceinline__ void split2h(float x0, float x1, unsigned& hu, unsigned& lu) {
    __half h0 = __float2half_rn(x0), h1 = __float2half_rn(x1);
    __half l0 = __float2half_rn(x0 - __half2float(h0));
    __half l1 = __float2half_rn(x1 - __half2float(h1));
    hu = (unsigned)__half_as_ushort(h0) | ((unsigned)__half_as_ushort(h1) << 16);
    lu = (unsigned)__half_as_ushort(l0) | ((unsigned)__half_as_ushort(l1) << 16);
}
__device__ __forceinline__ void split8h(const float* v, uint4& hv, uint4& lv) {
    unsigned hu[4], lu[4];
#pragma unroll
    for (int j = 0; j < 4; j++) split2h(v[2 * j], v[2 * j + 1], hu[j], lu[j]);
    hv = make_uint4(hu[0], hu[1], hu[2], hu[3]);
    lv = make_uint4(lu[0], lu[1], lu[2], lu[3]);
}
__device__ __forceinline__ uint4 cvt8h(const float* v) {
    unsigned u[4];
#pragma unroll
    for (int j = 0; j < 4; j++) {
        __half h0 = __float2half_rn(v[2 * j]), h1 = __float2half_rn(v[2 * j + 1]);
        u[j] = (unsigned)__half_as_ushort(h0) | ((unsigned)__half_as_ushort(h1) << 16);
    }
    return make_uint4(u[0], u[1], u[2], u[3]);
}

// ---------------------------------------------------------------------------
// Packers
// ---------------------------------------------------------------------------
__global__ __launch_bounds__(256) void pack_split(
    const float* __restrict__ X, char* __restrict__ P)
{
    const int gid = blockIdx.x * 256 + threadIdx.x;
    const int m   = gid >> 7;
    const int rem = gid & 127;
    const int c   = rem >> 2;
    const int c16 = rem & 3;
    const float* src = X + (size_t)m * DM + c * KC + c16 * 8;
    float v[8];
    float4 a = *(const float4*)src;
    float4 b = *(const float4*)(src + 4);
    v[0] = a.x; v[1] = a.y; v[2] = a.z; v[3] = a.w;
    v[4] = b.x; v[5] = b.y; v[6] = b.z; v[7] = b.w;
    uint4 hv, lv;
    split8h(v, hv, lv);
    char* dst = P + PKA((m >> 7), c) + (m & 127) * (ARS * 2) + c16 * 16;
    *(uint4*)dst = hv;
    *(uint4*)(dst + MATB) = lv;
}

__global__ __launch_bounds__(256) void pack_w4(
    const float* __restrict__ W0, const float* __restrict__ W1,
    const float* __restrict__ W2, const float* __restrict__ W3,
    char* __restrict__ P)
{
    const int gid = blockIdx.x * 256 + threadIdx.x;
    const int wsel = gid >> 17;
    const int g = gid & 131071;
    const float* W = (wsel == 0) ? W0 : (wsel == 1) ? W1 : (wsel == 2) ? W2 : W3;
    const int m   = g >> 7;
    const int rem = g & 127;
    const int c   = rem >> 2;
    const int c16 = rem & 3;
    const float* src = W + (size_t)m * DM + c * KC + c16 * 8;
    float v[8];
    float4 a = *(const float4*)src;
    float4 b = *(const float4*)(src + 4);
    v[0] = a.x; v[1] = a.y; v[2] = a.z; v[3] = a.w;
    v[4] = b.x; v[5] = b.y; v[6] = b.z; v[7] = b.w;
    uint4 hv = cvt8h(v);
    char* dst = P + PKB(wsel * 8 + (m >> 7), c) + (m & 127) * (ARS * 2) + c16 * 16;
    *(uint4*)dst = hv;
}

// ---------------------------------------------------------------------------
// mma.sync GEMM: A = 2-term fp16 (hi|lo), B = single fp16 -> 2 MMA terms.
// ---------------------------------------------------------------------------
__global__ __launch_bounds__(256) void gemm_mma(
    const char* __restrict__ Ap, const char* __restrict__ Bp,
    float* __restrict__ C, int N, int layout)
{
    extern __shared__ char smc[];
    const unsigned sb = smem_u32(smc);
    const unsigned sdata = sb + 128;
    const int tid = threadIdx.x;
    const int wid = tid >> 5;
    const int lane = tid & 31;
    const int bm = blockIdx.y, bn = blockIdx.x;
    const int wm = wid & 1;
    const int wn = wid >> 1;

    if (tid == 0) {
        MBAR_INIT(sb + 0, 1);
        MBAR_INIT(sb + 8, 1);
        MBAR_INIT(sb + 16, 1);
        MBAR_INIT(sb + 24, 1);
    }
    __syncthreads();

    auto issue = [&](int c, int s) {
        unsigned mb = sb + s * 8;
        MBAR_EXPECT(mb, STGB);
        unsigned dst = sdata + s * STGB;
        CP_BULK(dst,         Ap + PKA(bm, c), PAIRB, mb);
        CP_BULK(dst + PAIRB, Bp + PKB(bn, c), MATB, mb);
    };

    if (tid == 0) { issue(0, 0); issue(1, 1); issue(2, 2); }

    float d[16][4];
#pragma unroll
    for (int f = 0; f < 16; f++)
#pragma unroll
        for (int j = 0; j < 4; j++) d[f][j] = 0.f;

    for (int c = 0; c < NBK; c++) {
        const int s = c % NSTG;
        MBAR_WAIT(sb + s * 8, (c / NSTG) & 1);

        const unsigned base = sdata + s * STGB;
#pragma unroll
        for (int kk = 0; kk < KC; kk += 16) {
            unsigned Ahf[4][4], Alf[4][4];
#pragma unroll
            for (int fm = 0; fm < 4; fm++) {
                unsigned row = wm * 64 + fm * 16 + (lane & 15);
                unsigned col = kk + (lane >> 4) * 8;
                unsigned addr = base + row * (ARS * 2) + col * 2;
                ldsm_x4(Ahf[fm], addr);
                ldsm_x4(Alf[fm], addr + MATB);
            }
            unsigned Bf[4][2];
#pragma unroll
            for (int fnp = 0; fnp < 2; fnp++) {
                unsigned row = wn * 32 + fnp * 16 + (lane & 15);
                unsigned col = kk + (lane >> 4) * 8;
                unsigned addr = base + PAIRB + row * (ARS * 2) + col * 2;
                unsigned bH[4];
                ldsm_x4(bH, addr);
                Bf[2 * fnp][0] = bH[0]; Bf[2 * fnp][1] = bH[2];
                Bf[2 * fnp + 1][0] = bH[1]; Bf[2 * fnp + 1][1] = bH[3];
            }
#pragma unroll
            for (int fm = 0; fm < 4; fm++)
#pragma unroll
                for (int fn = 0; fn < 4; fn++) {
                    float* acc = d[fm * 4 + fn];
                    mma_f16(acc, Ahf[fm], Bf[fn]);
                    mma_f16(acc, Alf[fm], Bf[fn]);
                }
        }
        __syncthreads();
        if (tid == 0 && c + 3 < NBK) issue(c + 3, (c + 3) % NSTG);
    }

    const int mloc0 = bm * 128 + wm * 64 + (lane >> 2);
    const int nloc0 = bn * 128 + wn * 32 + (lane & 3) * 2;
#pragma unroll
    for (int fm = 0; fm < 4; fm++) {
#pragma unroll
        for (int fn = 0; fn < 4; fn++) {
            const float* acc = d[fm * 4 + fn];
            const int n = nloc0 + fn * 8;
#pragma unroll
            for (int rr = 0; rr < 2; rr++) {
                const int m = mloc0 + fm * 16 + rr * 8;
                float2 v = {acc[rr * 2], acc[rr * 2 + 1]};
                if (layout == 0) {
                    *(float2*)(C + (size_t)m * N + n) = v;
                } else {
                    const int which = n >> 10;
                    const int nn = n & 1023;
                    const int h = nn >> 6, dd = nn & 63;
                    const int bb = m >> 11, t = m & 2047;
                    float* dst = C + (size_t)which * (BH * T_SEQ * HD)
                               + (((size_t)(bb * NH + h) * T_SEQ + t) * HD + dd);
                    *(float2*)dst = v;
                }
            }
        }
    }
}

// ---------------------------------------------------------------------------
// Pass A: G_c[d1][d2] = sum_b gamma^(L-b) K[b][d1] V[b][d2]
// 64 threads, 8x8 tile per thread (4 LDS.128 per 64 FMA).
// ---------------------------------------------------------------------------
__global__ __launch_bounds__(64) void chunk_state(
    const float* __restrict__ K, const float* __restrict__ V,
    float* __restrict__ G)
{
    __shared__ __align__(16) float Ks[L_CH][HD];
    __shared__ __align__(16) float Vs[L_CH][HD];

    const int c  = blockIdx.x;
    const int bh = blockIdx.y;
    const int h  = bh & (NH - 1);
    const int tid = threadIdx.x;
    const int rB = (tid >> 3) * 8;   // 0..56
    const int cB = (tid & 7) * 8;    // 0..56

    const double g_d = 1.0 - exp2(-5.0 - 0.5 * (double)h);
    const float lg = (float)log2(g_d);

    const float* Kg = K + ((size_t)bh * T_SEQ + c * L_CH) * HD;
    const float* Vg = V + ((size_t)bh * T_SEQ + c * L_CH) * HD;
#pragma unroll
    for (int u = 0; u < 16; u++) {
        int idx = tid + u * 64;        // float4 index 0..1023
        int t = idx >> 4;
        int d4 = (idx & 15) * 4;
        float w = exp2f((float)(L_CH - t) * lg);
        float4 kv = *(const float4*)(Kg + t * HD + d4);
        kv.x *= w; kv.y *= w; kv.z *= w; kv.w *= w;
        *(float4*)&Ks[t][d4] = kv;
        *(float4*)&Vs[t][d4] = *(const float4*)(Vg + t * HD + d4);
    }
    __syncthreads();

    float acc[8][8];
#pragma unroll
    for (int i = 0; i < 8; i++)
#pragma unroll
        for (int j = 0; j < 8; j++) acc[i][j] = 0.f;

#pragma unroll 2
    for (int k = 0; k < L_CH; k++) {
        float4 a0 = *(const float4*)&Ks[k][rB];
        float4 a1 = *(const float4*)&Ks[k][rB + 4];
        float4 b0 = *(const float4*)&Vs[k][cB];
        float4 b1 = *(const float4*)&Vs[k][cB + 4];
        float ar[8] = {a0.x, a0.y, a0.z, a0.w, a1.x, a1.y, a1.z, a1.w};
        float br[8] = {b0.x, b0.y, b0.z, b0.w, b1.x, b1.y, b1.z, b1.w};
#pragma unroll
        for (int i = 0; i < 8; i++)
#pragma unroll
            for (int j = 0; j < 8; j++)
                acc[i][j] += ar[i] * br[j];
    }

    float* Gg = G + ((size_t)bh * NCH + c) * HD * HD;
#pragma unroll
    for (int i = 0; i < 8; i++) {
        float4 v0 = {acc[i][0], acc[i][1], acc[i][2], acc[i][3]};
        float4 v1 = {acc[i][4], acc[i][5], acc[i][6], acc[i][7]};
        *(float4*)&Gg[(rB + i) * HD + cB] = v0;
        *(float4*)&Gg[(rB + i) * HD + cB + 4] = v1;
    }
}

// ---------------------------------------------------------------------------
// Pass B: S_0 = 0 ; S_c = gamma^L * S_{c-1} + G_{c-1}
// ---------------------------------------------------------------------------
__global__ __launch_bounds__(256) void state_scan(
    const float* __restrict__ G, float* __restrict__ S)
{
    const int bh = blockIdx.x;
    const int h  = bh & (NH - 1);
    const int tid = threadIdx.x;
    const double g_d = 1.0 - exp2(-5.0 - 0.5 * (double)h);
    const float decL = (float)exp2((double)L_CH * log2(g_d));

    const size_t base = (size_t)bh * NCH * HD * HD;
    float s[16];
#pragma unroll
    for (int u = 0; u < 16; u++) s[u] = 0.f;

    for (int c = 0; c < NCH; c++) {
        const size_t off = base + (size_t)c * HD * HD;
#pragma unroll
        for (int u = 0; u < 16; u++) {
            int e = tid + u * 256;
            S[off + e] = s[u];
            s[u] = s[u] * decL + G[off + e];
        }
    }
}

// ---------------------------------------------------------------------------
// Pass C: O = gamma^a * (Q/8) @ S_c + intra-chunk decayed quadratic
// Merged Q-loops (Q@St and Q@Kt share Q loads) + fused GN partial.
// ---------------------------------------------------------------------------
__global__ __launch_bounds__(256) void retention_chunk(
    const float* __restrict__ Q, const float* __restrict__ K,
    const float* __restrict__ V, const float* __restrict__ S,
    float* __restrict__ O)
{
    extern __shared__ __align__(16) float sm[];
    float* Qs = sm;
    float* Kt = sm + 4096;
    float* Vs = sm + 8192;
    float* Ss = sm + 12288;
    float* St = sm + 16384;

    const int c  = blockIdx.x;
    const int bh = blockIdx.y;
    const int h  = bh & (NH - 1);
    const int r0 = c * L_CH;
    const int tid = threadIdx.x;
    const int rB = (tid >> 4) * 4;
    const int cB = (tid & 15) * 4;

    const double g_d = 1.0 - exp2(-5.0 - 0.5 * (double)h);
    const float lg = (float)log2(g_d);

    const float* Qg = Q + ((size_t)bh * T_SEQ + r0) * HD;
    const float* Kg = K + ((size_t)bh * T_SEQ + r0) * HD;
    const float* Vg = V + ((size_t)bh * T_SEQ + r0) * HD;
    const float* Sg = S + ((size_t)bh * NCH + c) * HD * HD;

#pragma unroll
    for (int u = 0; u < 4; u++) {
        int idx = tid + u * 256;
        int t = idx >> 4;
        int d4 = (idx & 15) * 4;
        *(float4*)&Qs[t * 64 + d4] = *(const float4*)(Qg + t * HD + d4);
        float4 kv = *(const float4*)(Kg + t * HD + d4);
        Kt[(d4 + 0) * 64 + t] = kv.x;
        Kt[(d4 + 1) * 64 + t] = kv.y;
        Kt[(d4 + 2) * 64 + t] = kv.z;
        Kt[(d4 + 3) * 64 + t] = kv.w;
        *(float4*)&Vs[t * 64 + d4] = *(const float4*)(Vg + t * HD + d4);
        *(float4*)&St[t * 64 + d4] = *(const float4*)(Sg + t * HD + d4);
    }
    __syncthreads();

    float acc[4][4], s[4][4];
#pragma unroll
    for (int i = 0; i < 4; i++)
#pragma unroll
        for (int j = 0; j < 4; j++) { acc[i][j] = 0.f; s[i][j] = 0.f; }

    // merged: acc += Q @ St ; s += Q @ Kt   (shared Q loads)
#pragma unroll 4
    for (int k = 0; k < HD; k++) {
        float a0 = Qs[(rB + 0) * 64 + k];
        float a1 = Qs[(rB + 1) * 64 + k];
        float a2 = Qs[(rB + 2) * 64 + k];
        float a3 = Qs[(rB + 3) * 64 + k];
        float4 bq = *(const float4*)&St[k * 64 + cB];
        acc[0][0] += a0 * bq.x; acc[0][1] += a0 * bq.y; acc[0][2] += a0 * bq.z; acc[0][3] += a0 * bq.w;
        acc[1][0] += a1 * bq.x; acc[1][1] += a1 * bq.y; acc[1][2] += a1 * bq.z; acc[1][3] += a1 * bq.w;
        acc[2][0] += a2 * bq.x; acc[2][1] += a2 * bq.y; acc[2][2] += a2 * bq.z; acc[2][3] += a2 * bq.w;
        acc[3][0] += a3 * bq.x; acc[3][1] += a3 * bq.y; acc[3][2] += a3 * bq.z; acc[3][3] += a3 * bq.w;
        float4 bk = *(const float4*)&Kt[k * 64 + cB];
        s[0][0] += a0 * bk.x; s[0][1] += a0 * bk.y; s[0][2] += a0 * bk.z; s[0][3] += a0 * bk.w;
        s[1][0] += a1 * bk.x; s[1][1] += a1 * bk.y; s[1][2] += a1 * bk.z; s[1][3] += a1 * bk.w;
        s[2][0] += a2 * bk.x; s[2][1] += a2 * bk.y; s[2][2] += a2 * bk.z; s[2][3] += a2 * bk.w;
        s[3][0] += a3 * bk.x; s[3][1] += a3 * bk.y; s[3][2] += a3 * bk.z; s[3][3] += a3 * bk.w;
    }

#pragma unroll
    for (int i = 0; i < 4; i++) {
        float f = exp2f((float)(rB + i) * lg) * 0.125f;
#pragma unroll
        for (int j = 0; j < 4; j++) acc[i][j] *= f;
    }

#pragma unroll
    for (int i = 0; i < 4; i++) {
#pragma unroll
        for (int j = 0; j < 4; j++) {
            int di = (rB + i) - (cB + j);
            float dec = (di >= 0) ? exp2f((float)di * lg) : 0.f;
            Ss[(rB + i) * 64 + (cB + j)] = s[i][j] * 0.125f * dec;
        }
    }
    __syncthreads();

#pragma unroll 4
    for (int k = 0; k < L_CH; k++) {
        float a0 = Ss[(rB + 0) * 64 + k];
        float a1 = Ss[(rB + 1) * 64 + k];
        float a2 = Ss[(rB + 2) * 64 + k];
        float a3 = Ss[(rB + 3) * 64 + k];
        float4 bv = *(const float4*)&Vs[k * 64 + cB];
        acc[0][0] += a0 * bv.x; acc[0][1] += a0 * bv.y; acc[0][2] += a0 * bv.z; acc[0][3] += a0 * bv.w;
        acc[1][0] += a1 * bv.x; acc[1][1] += a1 * bv.y; acc[1][2] += a1 * bv.z; acc[1][3] += a1 * bv.w;
        acc[2][0] += a2 * bv.x; acc[2][1] += a2 * bv.y; acc[2][2] += a2 * bv.z; acc[2][3] += a2 * bv.w;
        acc[3][0] += a3 * bv.x; acc[3][1] += a3 * bv.y; acc[3][2] += a3 * bv.z; acc[3][3] += a3 * bv.w;
    }

    float* Og = O + ((size_t)bh * T_SEQ + r0) * HD;
#pragma unroll
    for (int i = 0; i < 4; i++) {
        float4 v = {acc[i][0], acc[i][1], acc[i][2], acc[i][3]};
        *(float4*)&Og[(rB + i) * 64 + cB] = v;
    }

    // fused GN partial
    double ds = 0.0, ds2 = 0.0;
#pragma unroll
    for (int i = 0; i < 4; i++)
#pragma unroll
        for (int j = 0; j < 4; j++) {
            double x = (double)acc[i][j];
            ds += x; ds2 += x * x;
        }
    __syncthreads();
    double* shd  = (double*)sm;
    double* shd2 = (double*)sm + 256;
    shd[tid] = ds; shd2[tid] = ds2;
    __syncthreads();
    for (int off = 128; off > 0; off >>= 1) {
        if (tid < off) { shd[tid] += shd[tid + off]; shd2[tid] += shd2[tid + off]; }
        __syncthreads();
    }
    if (tid == 0) {
        g_PS[bh * NCH + c]  = shd[0];
        g_PS2[bh * NCH + c] = shd2[0];
    }
}

// ---------------------------------------------------------------------------
// GroupNorm finalize + apply
// ---------------------------------------------------------------------------
__global__ void gn_finalize()
{
    const int bh = blockIdx.x;
    const int tid = threadIdx.x;   // 32 threads
    double s  = g_PS[bh * NCH + tid];
    double s2 = g_PS2[bh * NCH + tid];
#pragma unroll
    for (int off = 16; off > 0; off >>= 1) {
        s  += __shfl_down_sync(0xffffffff, s,  off);
        s2 += __shfl_down_sync(0xffffffff, s2, off);
    }
    if (tid == 0) {
        const double N = (double)(T_SEQ * HD);
        double mu  = s / N;
        double var = s2 / N - mu * mu;
        g_MU[bh] = (float)mu;
        g_RS[bh] = (float)rsqrt(var + 1e-5);
    }
}

__global__ __launch_bounds__(256) void gn_apply(
    const float* __restrict__ O, const float* __restrict__ gw,
    const float* __restrict__ gb, char* __restrict__ YP)
{
    const int f = blockIdx.x * 256 + threadIdx.x;
    const int bh = f >> 15;
    const int rem = f & 32767;
    const int t = rem >> 4;
    const int d4 = (rem & 15) * 4;
    const int b = bh >> 4, h = bh & 15;

    const float mu = g_MU[bh], rs = g_RS[bh];
    float4 v = *(const float4*)(O + ((size_t)bh * T_SEQ + t) * HD + d4);
    float4 w = *(const float4*)(gw + h * HD + d4);
    float4 bb = *(const float4*)(gb + h * HD + d4);
    float r[4];
    r[0] = (v.x - mu) * rs * w.x + bb.x;
    r[1] = (v.y - mu) * rs * w.y + bb.y;
    r[2] = (v.z - mu) * rs * w.z + bb.z;
    r[3] = (v.w - mu) * rs * w.w + bb.w;

    unsigned hu[2], lu[2];
    split2h(r[0], r[1], hu[0], lu[0]);
    split2h(r[2], r[3], hu[1], lu[1]);
    const int m = b * T_SEQ + t;
    const int k0 = h * HD + d4;
    char* dst = YP + PKA(m >> 7, k0 >> 5) + (m & 127) * (ARS * 2) + (k0 & 31) * 2;
    uint2 hv = {hu[0], hu[1]};
    uint2 lv = {lu[0], lu[1]};
    *(uint2*)dst = hv;
    *(uint2*)(dst + MATB) = lv;
}

// ---------------------------------------------------------------------------
extern "C" void kernel_launch(void* const* d_in, const int* in_sizes, int n_in,
                              void* d_out, int out_size)
{
    const float* x   = (const float*)d_in[0];
    const float* Wq  = (const float*)d_in[1];
    const float* Wk  = (const float*)d_in[2];
    const float* Wv  = (const float*)d_in[3];
    const float* Wo  = (const float*)d_in[4];
    const float* gnw = (const float*)d_in[5];
    const float* gnb = (const float*)d_in[6];
    float* out = (float*)d_out;

    float *qkv, *o, *gg, *ss;
    char *xp, *wp, *yp;
    cudaGetSymbolAddress((void**)&qkv, g_QKV);
    cudaGetSymbolAddress((void**)&o, g_O);
    cudaGetSymbolAddress((void**)&gg, g_G);
    cudaGetSymbolAddress((void**)&ss, g_S);
    cudaGetSymbolAddress((void**)&xp, g_XP);
    cudaGetSymbolAddress((void**)&wp, g_WP);
    cudaGetSymbolAddress((void**)&yp, g_YP);

    float* q = qkv;
    float* k = qkv + 1 * (size_t)BH * T_SEQ * HD;
    float* v = qkv + 2 * (size_t)BH * T_SEQ * HD;

    const int gemm_smem = 128 + NSTG * STGB;   // 123008
    cudaFuncSetAttribute(gemm_mma, cudaFuncAttributeMaxDynamicSharedMemorySize, gemm_smem);
    cudaFuncSetAttribute(retention_chunk, cudaFuncAttributeMaxDynamicSharedMemorySize, 81920);

    pack_split<<<2048, 256>>>(x, xp);
    pack_w4<<<2048, 256>>>(Wq, Wk, Wv, Wo, wp);

    dim3 gQKV(3 * DM / 128, MROWS / 128);   // (24, 32)
    gemm_mma<<<gQKV, 256, gemm_smem>>>(xp, wp, qkv, 3 * DM, 1);

    chunk_state<<<dim3(NCH, BH), 64>>>(k, v, gg);
    state_scan<<<BH, 256>>>(gg, ss);
    retention_chunk<<<dim3(NCH, BH), 256, 81920>>>(q, k, v, ss, o);

    gn_finalize<<<BH, 32>>>();
    gn_apply<<<(MROWS * DM) / (4 * 256), 256>>>(o, gnw, gnb, yp);

    dim3 gO(DM / 128, MROWS / 128);         // (8, 32)
    gemm_mma<<<gO, 256, gemm_smem>>>(yp, wp + PKB(24, 0), out, DM, 0);
}